// round 10
// baseline (speedup 1.0000x reference)
#include <cuda_runtime.h>
#include <math.h>

#define BB   8
#define NN   64
#define CO   248
#define RO   496
#define FFW  128
#define TABN 1024

// -------- device scratch --------
__device__ float g_Wfe[6 * 101 * 80];          // contracted radial weights per embedding (pad lu->80)
__device__ float g_H2T[100 * TABN];            // h2 table transposed [k][d]
__device__ __align__(16) float g_T[6 * TABN * 72];   // t table [e][d][72]
__device__ float g_featsT[CO * BB * NN];       // feats [248][512]
__device__ float g_x2p[8 * 256 * 512];         // residual GEMM partials [kc][n pad 256][m]
__device__ float g_pooled[BB * RO];

__device__ __forceinline__ float sp5(float x) {
    float z = 5.0f * x;
    return 0.2f * (fmaxf(z, 0.0f) + __logf(1.0f + __expf(-fabsf(z))));
}

// ---------------- Wfe[e][k][lu] = sum_v rW3[k, lu*32+v] * emb[e,v] / sqrt(32); row 100 = rb3 ----------------
__global__ void kWfe(const float* __restrict__ rW3, const float* __restrict__ rb3,
                     const float* __restrict__ emb) {
    __shared__ float sRowT[32 * 73];
    __shared__ float sEmb[32];
    int e  = blockIdx.x / 101;
    int kk = blockIdx.x % 101;
    int tid = threadIdx.x;  // 128
    const float* src = (kk < 100) ? (rW3 + kk * 2304) : rb3;
    for (int idx = tid; idx < 2304; idx += 128) {
        int lu = idx >> 5, v = idx & 31;
        sRowT[v * 73 + lu] = src[idx];
    }
    if (tid < 32) sEmb[tid] = emb[e * 32 + tid];
    __syncthreads();
    if (tid < 80) {
        float out = 0.0f;
        if (tid < 72) {
            float acc = 0.0f;
            #pragma unroll
            for (int v = 0; v < 32; v++) acc += sRowT[v * 73 + tid] * sEmb[v];
            out = acc * 0.17677669529663687f;
        }
        g_Wfe[e * 8080 + kk * 80 + tid] = out;
    }
}

// ---------------- radial MLP table: H2T[k][d] over 1024 d-samples in [0,2] ----------------
__global__ void __launch_bounds__(256) kH2tab(
    const float* __restrict__ rW1, const float* __restrict__ rb1,
    const float* __restrict__ rW2, const float* __restrict__ rb2) {
    __shared__ float sW2[10000];
    __shared__ float sh1[800];   // [k][s]
    __shared__ float sBa[24];    // [r][s]
    const int tid = threadIdx.x;
    const int d0 = blockIdx.x * 8;
    for (int idx = tid; idx < 10000; idx += 256) sW2[idx] = rW2[idx];
    if (tid < 24) {
        int s = tid & 7, r = tid >> 3;
        float d = (float)(d0 + s) * (2.0f / 1023.0f);
        float uu = fabsf(d - (float)r);
        float c = __cosf(1.57079632679f * uu);
        sBa[r * 8 + s] = (uu < 1.0f) ? c * c : 0.0f;
    }
    __syncthreads();
    for (int idx = tid; idx < 800; idx += 256) {
        int s = idx & 7, k = idx >> 3;
        float z = rb1[k] + sBa[s] * rW1[k] + sBa[8 + s] * rW1[100 + k] + sBa[16 + s] * rW1[200 + k];
        sh1[k * 8 + s] = sp5(z);
    }
    __syncthreads();
    for (int idx = tid; idx < 800; idx += 256) {
        int s = idx / 100, k2 = idx - s * 100;
        float acc = rb2[k2];
        #pragma unroll 4
        for (int k1 = 0; k1 < 100; k1++) acc += sh1[k1 * 8 + s] * sW2[k1 * 100 + k2];
        g_H2T[k2 * TABN + d0 + s] = sp5(acc);
    }
}

// ---------------- T[e][d][lu] = H2[d] @ Wfe[e] + bias ----------------
#define TT_SMEM ((8080 + 6400) * 4)
__global__ void __launch_bounds__(256) kTtab() {
    extern __shared__ float sm[];
    float* sWf = sm;           // 8080
    float* sA  = sm + 8080;    // [k][dd] 100*64
    const int tid = threadIdx.x;
    const int e = blockIdx.x >> 4, d0 = (blockIdx.x & 15) * 64;
    {
        const float4* srcW = (const float4*)(g_Wfe + e * 8080);
        float4* dstW = (float4*)sWf;
        for (int idx = tid; idx < 2020; idx += 256) dstW[idx] = srcW[idx];
    }
    for (int idx = tid; idx < 6400; idx += 256) {
        int k = idx >> 6, dd = idx & 63;
        sA[idx] = g_H2T[k * TABN + d0 + dd];
    }
    __syncthreads();
    const int dg = tid >> 4, lg = tid & 15;
    const int dd0 = dg << 2, lu0 = lg * 5;
    float a0[5], a1[5], a2[5], a3[5];
    #pragma unroll
    for (int t = 0; t < 5; t++) {
        float bb = sWf[8000 + lu0 + t];
        a0[t] = bb; a1[t] = bb; a2[t] = bb; a3[t] = bb;
    }
    #pragma unroll 2
    for (int k = 0; k < 100; k++) {
        float4 a = *(const float4*)(sA + (k << 6) + dd0);
        const float* wr = sWf + k * 80 + lu0;
        #pragma unroll
        for (int t = 0; t < 5; t++) {
            float w = wr[t];
            a0[t] += a.x * w; a1[t] += a.y * w; a2[t] += a.z * w; a3[t] += a.w * w;
        }
    }
    #pragma unroll
    for (int t = 0; t < 5; t++) {
        int lu = lu0 + t;
        if (lu < 72) {
            g_T[((e << 10) + d0 + dd0 + 0) * 72 + lu] = a0[t];
            g_T[((e << 10) + d0 + dd0 + 1) * 72 + lu] = a1[t];
            g_T[((e << 10) + d0 + dd0 + 2) * 72 + lu] = a2[t];
            g_T[((e << 10) + d0 + dd0 + 3) * 72 + lu] = a3[t];
        }
    }
}

// ---------------- gather: per (b,i): lerp-combined T rows, contract with mask*Y ----------------
__global__ void __launch_bounds__(512) kGather(const float* __restrict__ xyz,
                                               const int* __restrict__ feat,
                                               const float* __restrict__ emb) {
    __shared__ float sTl[64 * 72];    // lerp-combined T row per neighbor (18 KB)
    __shared__ float sY[64 * 12];     // mask*Y per neighbor
    __shared__ float sF2[64 * 2];     // lerp weights (1-f, f)
    __shared__ int   sBase[64];
    __shared__ float sPar[216];       // jj-half partials
    __shared__ float sMsum[2];
    __shared__ float sInv;
    const int bi = blockIdx.x;
    const int b = bi >> 6, i = bi & 63;
    const int tid = threadIdx.x;  // 512
    if (tid < 64) {
        int jj = tid;
        float dx = xyz[(b * 64 + jj) * 3 + 0] - xyz[bi * 3 + 0];
        float dy = xyz[(b * 64 + jj) * 3 + 1] - xyz[bi * 3 + 1];
        float dz = xyz[(b * 64 + jj) * 3 + 2] - xyz[bi * 3 + 2];
        float d = sqrtf(dx * dx + dy * dy + dz * dz + 1e-8f);
        float m = (d < 2.0f && jj != i) ? 1.0f : 0.0f;
        float inv = 1.0f / d;
        float ux = dx * inv, uy = dy * inv, uz = dz * inv;
        float db = d * 511.5f;
        int bin = (int)db;
        bin = (bin > 1022) ? 1022 : bin;
        float f = db - (float)bin;
        sBase[jj] = (feat[b * 64 + jj] * TABN + bin) * 72;
        sF2[2 * jj]     = 1.0f - f;
        sF2[2 * jj + 1] = f;
        float* yr = sY + jj * 12;
        yr[0] = m * 0.28209479177f;
        yr[1] = m * 0.48860251190f * uy;
        yr[2] = m * 0.48860251190f * uz;
        yr[3] = m * 0.48860251190f * ux;
        yr[4] = m * 1.09254843059f * ux * uy;
        yr[5] = m * 1.09254843059f * uy * uz;
        yr[6] = m * 0.31539156525f * (3.0f * uz * uz - 1.0f);
        yr[7] = m * 1.09254843059f * ux * uz;
        yr[8] = m * 0.54627421529f * (ux * ux - uy * uy);
        float s = m;
        #pragma unroll
        for (int o = 16; o > 0; o >>= 1) s += __shfl_down_sync(0xffffffffu, s, o);
        if ((tid & 31) == 0) sMsum[tid >> 5] = s;
    }
    __syncthreads();
    if (tid == 0) sInv = rsqrtf(fmaxf(sMsum[0] + sMsum[1], 1.0f));
    // staging + lerp: 8 threads per neighbor; rows bin/bin+1 are adjacent (stride 18 float4)
    {
        const int jj = tid >> 3, seg = tid & 7;
        const float4* r1 = (const float4*)(g_T + sBase[jj]);
        const float f1 = sF2[2 * jj], f2 = sF2[2 * jj + 1];
        float4* dst = (float4*)(sTl + jj * 72);
        #pragma unroll
        for (int q = seg; q < 18; q += 8) {
            float4 a = r1[q], c = r1[q + 18];
            float4 o;
            o.x = f1 * a.x + f2 * c.x;
            o.y = f1 * a.y + f2 * c.y;
            o.z = f1 * a.z + f2 * c.z;
            o.w = f1 * a.w + f2 * c.w;
            dst[q] = o;
        }
    }
    __syncthreads();
    // contraction: 216 channels x 2 jj-halves
    {
        int ch = -1, jj0 = 0;
        if (tid < 216)                       { ch = tid;       jj0 = 0;  }
        else if (tid >= 256 && tid < 472)    { ch = tid - 256; jj0 = 32; }
        float acc = 0.0f;
        int lu = 0, ym = 0;
        if (ch >= 0) {
            if (ch < 24)      { lu = ch; ym = 0; }
            else if (ch < 96) { int q = ch - 24; int u = q / 3; ym = 1 + (q - u * 3); lu = 24 + u; }
            else              { int q = ch - 96; int u = q / 5; ym = 4 + (q - u * 5); lu = 48 + u; }
            #pragma unroll 8
            for (int jj = jj0; jj < jj0 + 32; jj++)
                acc += sY[jj * 12 + ym] * sTl[jj * 72 + lu];
            if (jj0 == 32) sPar[ch] = acc;
        }
        __syncthreads();
        if (ch >= 0 && jj0 == 0)
            g_featsT[(32 + ch) * 512 + bi] = (acc + sPar[ch]) * sInv;
        else if (tid >= 216 && tid < 248) {
            int c = tid - 216;
            g_featsT[c * 512 + bi] = emb[feat[bi] * 32 + c];
        }
    }
}

// ---------------- residual GEMM, K-split: 32 tiles (64m x 64n) x 8 K-chunks of 31 ----------------
__global__ void __launch_bounds__(256) kRes(const float* __restrict__ resW) {
    __shared__ float sA[31 * 64];   // featsT chunk [k][m]
    __shared__ float sB[31 * 64];   // resW  chunk [k][n]
    const int tid = threadIdx.x;
    const int tile = blockIdx.x & 31;
    const int kc   = blockIdx.x >> 5;
    const int m0 = (tile & 7) * 64;
    const int n0 = (tile >> 3) * 64;
    const int kb = kc * 31;
    const int tx = tid & 15, ty = tid >> 4;

    for (int idx = tid; idx < 1984; idx += 256) {
        int r = idx >> 6, mm = idx & 63;
        sA[idx] = g_featsT[(kb + r) * 512 + m0 + mm];
        int n = n0 + mm;
        sB[idx] = (n < CO) ? resW[(kb + r) * CO + n] : 0.0f;
    }
    __syncthreads();

    float acc[4][4];
    #pragma unroll
    for (int p = 0; p < 4; p++)
        #pragma unroll
        for (int q = 0; q < 4; q++) acc[p][q] = 0.0f;

    #pragma unroll
    for (int r = 0; r < 31; r++) {
        float4 a  = *(const float4*)(sA + (r << 6) + (tx << 2));
        float4 bv = *(const float4*)(sB + (r << 6) + (ty << 2));
        acc[0][0] += bv.x * a.x; acc[0][1] += bv.x * a.y; acc[0][2] += bv.x * a.z; acc[0][3] += bv.x * a.w;
        acc[1][0] += bv.y * a.x; acc[1][1] += bv.y * a.y; acc[1][2] += bv.y * a.z; acc[1][3] += bv.y * a.w;
        acc[2][0] += bv.z * a.x; acc[2][1] += bv.z * a.y; acc[2][2] += bv.z * a.z; acc[2][3] += bv.z * a.w;
        acc[3][0] += bv.w * a.x; acc[3][1] += bv.w * a.y; acc[3][2] += bv.w * a.z; acc[3][3] += bv.w * a.w;
    }

    #pragma unroll
    for (int p = 0; p < 4; p++) {
        int n = n0 + (ty << 2) + p;
        float4 st;
        st.x = acc[p][0]; st.y = acc[p][1]; st.z = acc[p][2]; st.w = acc[p][3];
        *(float4*)(g_x2p + ((kc << 8) + n) * 512 + m0 + (tx << 2)) = st;
    }
}

// ---------------- per-column: sum K-partials (+resb), BN+relu, per-b mean pool ----------------
__global__ void kPool(const float* __restrict__ gamma, const float* __restrict__ beta,
                      const float* __restrict__ resb) {
    __shared__ float sP[8];
    __shared__ float rs[8], rss[8];
    __shared__ float sScale, sShift;
    int c = blockIdx.x;        // 0..495
    int tid = threadIdx.x;     // 256
    int lane = tid & 31, w = tid >> 5;
    if (tid < 8) sP[tid] = 0.0f;

    float v0, v1;
    if (c < CO) {
        v0 = g_featsT[c * 512 + tid];
        v1 = g_featsT[c * 512 + 256 + tid];
    } else {
        int c2 = c - CO;
        float bb = resb[c2];
        v0 = bb; v1 = bb;
        #pragma unroll
        for (int q = 0; q < 8; q++) {
            const float* row = g_x2p + ((q << 8) + c2) * 512;
            v0 += row[tid];
            v1 += row[256 + tid];
        }
        float s = v0 + v1, ss = v0 * v0 + v1 * v1;
        #pragma unroll
        for (int o = 16; o > 0; o >>= 1) {
            s  += __shfl_down_sync(0xffffffffu, s, o);
            ss += __shfl_down_sync(0xffffffffu, ss, o);
        }
        if (lane == 0) { rs[w] = s; rss[w] = ss; }
        __syncthreads();
        if (tid == 0) {
            float S = 0.0f, SS = 0.0f;
            for (int q = 0; q < 8; q++) { S += rs[q]; SS += rss[q]; }
            float mu = S * (1.0f / 512.0f);
            float var = SS * (1.0f / 512.0f) - mu * mu;
            float sc = gamma[c2] * rsqrtf(var + 1e-5f);
            sScale = sc;
            sShift = beta[c2] - mu * sc;
        }
        __syncthreads();
        v0 = fmaxf(v0 * sScale + sShift, 0.0f);
        v1 = fmaxf(v1 * sScale + sShift, 0.0f);
    }
    __syncthreads();
    float p0 = v0, p1 = v1;
    #pragma unroll
    for (int o = 16; o > 0; o >>= 1) {
        p0 += __shfl_down_sync(0xffffffffu, p0, o);
        p1 += __shfl_down_sync(0xffffffffu, p1, o);
    }
    if (lane == 0) {
        atomicAdd(&sP[w >> 1], p0);
        atomicAdd(&sP[4 + (w >> 1)], p1);
    }
    __syncthreads();
    if (tid < 8) g_pooled[tid * RO + c] = sP[tid] * (1.0f / 64.0f);
}

// ---------------- fused head + output: single block, 1024 threads ----------------
__global__ void __launch_bounds__(1024) kHeadOut(
    const float* __restrict__ cW, const float* __restrict__ cb,
    const float* __restrict__ cg, const float* __restrict__ cbeta,
    const float* __restrict__ oW, const float* __restrict__ ob,
    float* __restrict__ out) {
    __shared__ float sAcc[8 * FFW * 8];   // [part][ff][b] 32 KB
    __shared__ float sC[FFW * 8];         // [ff][b] contributions
    const int tid = threadIdx.x;
    const int ff = tid & 127, part = tid >> 7;   // 8 parts x 62 c's
    float p[8];
    #pragma unroll
    for (int q = 0; q < 8; q++) p[q] = 0.0f;
    const int c0 = part * 62;
    for (int c = c0; c < c0 + 62; c++) {
        float wv = cW[c * FFW + ff];
        #pragma unroll
        for (int q = 0; q < 8; q++) p[q] += g_pooled[q * RO + c] * wv;
    }
    #pragma unroll
    for (int q = 0; q < 8; q++) sAcc[(part * FFW + ff) * 8 + q] = p[q];
    __syncthreads();
    if (tid < FFW) {
        float h[8];
        #pragma unroll
        for (int q = 0; q < 8; q++) h[q] = cb[tid];
        #pragma unroll
        for (int pp = 0; pp < 8; pp++)
            #pragma unroll
            for (int q = 0; q < 8; q++) h[q] += sAcc[(pp * FFW + tid) * 8 + q];
        float S = 0.0f, SS = 0.0f;
        #pragma unroll
        for (int q = 0; q < 8; q++) {
            h[q] = (h[q] > 0.0f) ? h[q] : 0.01f * h[q];
            S += h[q]; SS += h[q] * h[q];
        }
        float mu = S * 0.125f;
        float is = rsqrtf(SS * 0.125f - mu * mu + 1e-5f);
        float gg = cg[tid], bb = cbeta[tid], w = oW[tid];
        #pragma unroll
        for (int q = 0; q < 8; q++) {
            float v = (h[q] - mu) * is * gg + bb;
            v = (v > 0.0f) ? v : 0.01f * v;
            sC[tid * 8 + q] = v * w;
        }
    }
    __syncthreads();
    if (tid < 256) {
        int bq = tid >> 5, lane = tid & 31;
        float s = sC[lane * 8 + bq] + sC[(lane + 32) * 8 + bq]
                + sC[(lane + 64) * 8 + bq] + sC[(lane + 96) * 8 + bq];
        #pragma unroll
        for (int o = 16; o > 0; o >>= 1) s += __shfl_down_sync(0xffffffffu, s, o);
        if (lane == 0) out[bq] = 1.0f / (1.0f + __expf(-(s + ob[0])));
    }
}

extern "C" void kernel_launch(void* const* d_in, const int* in_sizes, int n_in,
                              void* d_out, int out_size) {
    const float* xyz   = (const float*)d_in[0];
    const int*   feat  = (const int*)  d_in[1];
    const float* emb   = (const float*)d_in[2];
    const float* rW1   = (const float*)d_in[3];
    const float* rb1   = (const float*)d_in[4];
    const float* rW2   = (const float*)d_in[5];
    const float* rb2   = (const float*)d_in[6];
    const float* rW3   = (const float*)d_in[7];
    const float* rb3   = (const float*)d_in[8];
    const float* resW  = (const float*)d_in[9];
    const float* resb  = (const float*)d_in[10];
    const float* resg  = (const float*)d_in[11];
    const float* resbe = (const float*)d_in[12];
    const float* cW    = (const float*)d_in[13];
    const float* cb    = (const float*)d_in[14];
    const float* cg    = (const float*)d_in[15];
    const float* cbe   = (const float*)d_in[16];
    const float* oW    = (const float*)d_in[17];
    const float* ob    = (const float*)d_in[18];
    float* out = (float*)d_out;

    cudaFuncSetAttribute(kTtab, cudaFuncAttributeMaxDynamicSharedMemorySize, TT_SMEM);

    kWfe<<<606, 128>>>(rW3, rb3, emb);
    kH2tab<<<128, 256>>>(rW1, rb1, rW2, rb2);
    kTtab<<<96, 256, TT_SMEM>>>();
    kGather<<<512, 512>>>(xyz, feat, emb);
    kRes<<<256, 256>>>(resW);
    kPool<<<496, 256>>>(resg, resbe, resb);
    kHeadOut<<<1, 1024>>>(cW, cb, cg, cbe, oW, ob, out);
}

// round 11
// speedup vs baseline: 1.1625x; 1.1625x over previous
#include <cuda_runtime.h>
#include <math.h>

#define BB   8
#define NN   64
#define CO   248
#define RO   496
#define FFW  128
#define TABN 1024

// -------- device scratch --------
__device__ float g_Wfe[6 * 101 * 80];          // contracted radial weights per embedding (pad lu->80)
__device__ float g_H2T[100 * TABN];            // h2 table transposed [k][d]
__device__ __align__(16) float g_T[6 * TABN * 72];   // t table [e][d][72]
__device__ float g_featsT[CO * BB * NN];       // feats [248][512]
__device__ float g_x2p[8 * 256 * 512];         // residual GEMM partials [kc][n pad 256][m]
__device__ float g_pooled[BB * RO];
__device__ float g_hpart[BB * FFW];            // head partials

__device__ __forceinline__ float sp5(float x) {
    float z = 5.0f * x;
    return 0.2f * (fmaxf(z, 0.0f) + __logf(1.0f + __expf(-fabsf(z))));
}

// ---------------- Wfe[e][k][lu] = sum_v rW3[k, lu*32+v] * emb[e,v] / sqrt(32); row 100 = rb3 ----------------
__global__ void kWfe(const float* __restrict__ rW3, const float* __restrict__ rb3,
                     const float* __restrict__ emb) {
    __shared__ float sRowT[32 * 73];
    __shared__ float sEmb[32];
    int e  = blockIdx.x / 101;
    int kk = blockIdx.x % 101;
    int tid = threadIdx.x;  // 128
    const float* src = (kk < 100) ? (rW3 + kk * 2304) : rb3;
    for (int idx = tid; idx < 2304; idx += 128) {
        int lu = idx >> 5, v = idx & 31;
        sRowT[v * 73 + lu] = src[idx];
    }
    if (tid < 32) sEmb[tid] = emb[e * 32 + tid];
    __syncthreads();
    if (tid < 80) {
        float out = 0.0f;
        if (tid < 72) {
            float acc = 0.0f;
            #pragma unroll
            for (int v = 0; v < 32; v++) acc += sRowT[v * 73 + tid] * sEmb[v];
            out = acc * 0.17677669529663687f;
        }
        g_Wfe[e * 8080 + kk * 80 + tid] = out;
    }
}

// ---------------- radial MLP table: H2T[k][d] over 1024 d-samples in [0,2] ----------------
__global__ void __launch_bounds__(256) kH2tab(
    const float* __restrict__ rW1, const float* __restrict__ rb1,
    const float* __restrict__ rW2, const float* __restrict__ rb2) {
    __shared__ float sW2[10000];
    __shared__ float sh1[800];   // [k][s]
    __shared__ float sBa[24];    // [r][s]
    const int tid = threadIdx.x;
    const int d0 = blockIdx.x * 8;
    for (int idx = tid; idx < 10000; idx += 256) sW2[idx] = rW2[idx];
    if (tid < 24) {
        int s = tid & 7, r = tid >> 3;
        float d = (float)(d0 + s) * (2.0f / 1023.0f);
        float uu = fabsf(d - (float)r);
        float c = __cosf(1.57079632679f * uu);
        sBa[r * 8 + s] = (uu < 1.0f) ? c * c : 0.0f;
    }
    __syncthreads();
    for (int idx = tid; idx < 800; idx += 256) {
        int s = idx & 7, k = idx >> 3;
        float z = rb1[k] + sBa[s] * rW1[k] + sBa[8 + s] * rW1[100 + k] + sBa[16 + s] * rW1[200 + k];
        sh1[k * 8 + s] = sp5(z);
    }
    __syncthreads();
    for (int idx = tid; idx < 800; idx += 256) {
        int s = idx / 100, k2 = idx - s * 100;
        float acc = rb2[k2];
        #pragma unroll 4
        for (int k1 = 0; k1 < 100; k1++) acc += sh1[k1 * 8 + s] * sW2[k1 * 100 + k2];
        g_H2T[k2 * TABN + d0 + s] = sp5(acc);
    }
}

// ---------------- T[e][d][lu] = H2[d] @ Wfe[e] + bias ----------------
#define TT_SMEM ((8080 + 6400) * 4)
__global__ void __launch_bounds__(256) kTtab() {
    extern __shared__ float sm[];
    float* sWf = sm;           // 8080
    float* sA  = sm + 8080;    // [k][dd] 100*64
    const int tid = threadIdx.x;
    const int e = blockIdx.x >> 4, d0 = (blockIdx.x & 15) * 64;
    {
        const float4* srcW = (const float4*)(g_Wfe + e * 8080);
        float4* dstW = (float4*)sWf;
        for (int idx = tid; idx < 2020; idx += 256) dstW[idx] = srcW[idx];
    }
    for (int idx = tid; idx < 6400; idx += 256) {
        int k = idx >> 6, dd = idx & 63;
        sA[idx] = g_H2T[k * TABN + d0 + dd];
    }
    __syncthreads();
    const int dg = tid >> 4, lg = tid & 15;
    const int dd0 = dg << 2, lu0 = lg * 5;
    float a0[5], a1[5], a2[5], a3[5];
    #pragma unroll
    for (int t = 0; t < 5; t++) {
        float bb = sWf[8000 + lu0 + t];
        a0[t] = bb; a1[t] = bb; a2[t] = bb; a3[t] = bb;
    }
    #pragma unroll 2
    for (int k = 0; k < 100; k++) {
        float4 a = *(const float4*)(sA + (k << 6) + dd0);
        const float* wr = sWf + k * 80 + lu0;
        #pragma unroll
        for (int t = 0; t < 5; t++) {
            float w = wr[t];
            a0[t] += a.x * w; a1[t] += a.y * w; a2[t] += a.z * w; a3[t] += a.w * w;
        }
    }
    #pragma unroll
    for (int t = 0; t < 5; t++) {
        int lu = lu0 + t;
        if (lu < 72) {
            g_T[((e << 10) + d0 + dd0 + 0) * 72 + lu] = a0[t];
            g_T[((e << 10) + d0 + dd0 + 1) * 72 + lu] = a1[t];
            g_T[((e << 10) + d0 + dd0 + 2) * 72 + lu] = a2[t];
            g_T[((e << 10) + d0 + dd0 + 3) * 72 + lu] = a3[t];
        }
    }
}

// ---------------- gather: per (b,i): lerp-combined T rows, contract with mask*Y ----------------
__global__ void __launch_bounds__(512) kGather(const float* __restrict__ xyz,
                                               const int* __restrict__ feat,
                                               const float* __restrict__ emb) {
    __shared__ float sTl[64 * 72];    // lerp-combined T row per neighbor (18 KB)
    __shared__ float sY[64 * 12];     // mask*Y per neighbor
    __shared__ float sF2[64 * 2];     // lerp weights (1-f, f)
    __shared__ int   sBase[64];
    __shared__ float sPar[216];       // jj-half partials
    __shared__ float sMsum[2];
    __shared__ float sInv;
    const int bi = blockIdx.x;
    const int b = bi >> 6, i = bi & 63;
    const int tid = threadIdx.x;  // 512
    if (tid < 64) {
        int jj = tid;
        float dx = xyz[(b * 64 + jj) * 3 + 0] - xyz[bi * 3 + 0];
        float dy = xyz[(b * 64 + jj) * 3 + 1] - xyz[bi * 3 + 1];
        float dz = xyz[(b * 64 + jj) * 3 + 2] - xyz[bi * 3 + 2];
        float d = sqrtf(dx * dx + dy * dy + dz * dz + 1e-8f);
        float m = (d < 2.0f && jj != i) ? 1.0f : 0.0f;
        float inv = 1.0f / d;
        float ux = dx * inv, uy = dy * inv, uz = dz * inv;
        float db = d * 511.5f;
        int bin = (int)db;
        bin = (bin > 1022) ? 1022 : bin;
        float f = db - (float)bin;
        sBase[jj] = (feat[b * 64 + jj] * TABN + bin) * 72;
        sF2[2 * jj]     = 1.0f - f;
        sF2[2 * jj + 1] = f;
        float* yr = sY + jj * 12;
        yr[0] = m * 0.28209479177f;
        yr[1] = m * 0.48860251190f * uy;
        yr[2] = m * 0.48860251190f * uz;
        yr[3] = m * 0.48860251190f * ux;
        yr[4] = m * 1.09254843059f * ux * uy;
        yr[5] = m * 1.09254843059f * uy * uz;
        yr[6] = m * 0.31539156525f * (3.0f * uz * uz - 1.0f);
        yr[7] = m * 1.09254843059f * ux * uz;
        yr[8] = m * 0.54627421529f * (ux * ux - uy * uy);
        float s = m;
        #pragma unroll
        for (int o = 16; o > 0; o >>= 1) s += __shfl_down_sync(0xffffffffu, s, o);
        if ((tid & 31) == 0) sMsum[tid >> 5] = s;
    }
    __syncthreads();
    if (tid == 0) sInv = rsqrtf(fmaxf(sMsum[0] + sMsum[1], 1.0f));
    // staging + lerp: 8 threads per neighbor; rows bin/bin+1 are adjacent (stride 18 float4)
    {
        const int jj = tid >> 3, seg = tid & 7;
        const float4* r1 = (const float4*)(g_T + sBase[jj]);
        const float f1 = sF2[2 * jj], f2 = sF2[2 * jj + 1];
        float4* dst = (float4*)(sTl + jj * 72);
        #pragma unroll
        for (int q = seg; q < 18; q += 8) {
            float4 a = r1[q], c = r1[q + 18];
            float4 o;
            o.x = f1 * a.x + f2 * c.x;
            o.y = f1 * a.y + f2 * c.y;
            o.z = f1 * a.z + f2 * c.z;
            o.w = f1 * a.w + f2 * c.w;
            dst[q] = o;
        }
    }
    __syncthreads();
    // contraction: 216 channels x 2 jj-halves
    {
        int ch = -1, jj0 = 0;
        if (tid < 216)                       { ch = tid;       jj0 = 0;  }
        else if (tid >= 256 && tid < 472)    { ch = tid - 256; jj0 = 32; }
        float acc = 0.0f;
        int lu = 0, ym = 0;
        if (ch >= 0) {
            if (ch < 24)      { lu = ch; ym = 0; }
            else if (ch < 96) { int q = ch - 24; int u = q / 3; ym = 1 + (q - u * 3); lu = 24 + u; }
            else              { int q = ch - 96; int u = q / 5; ym = 4 + (q - u * 5); lu = 48 + u; }
            #pragma unroll 8
            for (int jj = jj0; jj < jj0 + 32; jj++)
                acc += sY[jj * 12 + ym] * sTl[jj * 72 + lu];
            if (jj0 == 32) sPar[ch] = acc;
        }
        __syncthreads();
        if (ch >= 0 && jj0 == 0)
            g_featsT[(32 + ch) * 512 + bi] = (acc + sPar[ch]) * sInv;
        else if (tid >= 216 && tid < 248) {
            int c = tid - 216;
            g_featsT[c * 512 + bi] = emb[feat[bi] * 32 + c];
        }
    }
}

// ---------------- residual GEMM, K-split: 32 tiles (64m x 64n) x 8 K-chunks of 31 ----------------
__global__ void __launch_bounds__(256) kRes(const float* __restrict__ resW) {
    __shared__ float sA[31 * 64];   // featsT chunk [k][m]
    __shared__ float sB[31 * 64];   // resW  chunk [k][n]
    const int tid = threadIdx.x;
    const int tile = blockIdx.x & 31;
    const int kc   = blockIdx.x >> 5;
    const int m0 = (tile & 7) * 64;
    const int n0 = (tile >> 3) * 64;
    const int kb = kc * 31;
    const int tx = tid & 15, ty = tid >> 4;

    for (int idx = tid; idx < 1984; idx += 256) {
        int r = idx >> 6, mm = idx & 63;
        sA[idx] = g_featsT[(kb + r) * 512 + m0 + mm];
        int n = n0 + mm;
        sB[idx] = (n < CO) ? resW[(kb + r) * CO + n] : 0.0f;
    }
    __syncthreads();

    float acc[4][4];
    #pragma unroll
    for (int p = 0; p < 4; p++)
        #pragma unroll
        for (int q = 0; q < 4; q++) acc[p][q] = 0.0f;

    #pragma unroll
    for (int r = 0; r < 31; r++) {
        float4 a  = *(const float4*)(sA + (r << 6) + (tx << 2));
        float4 bv = *(const float4*)(sB + (r << 6) + (ty << 2));
        acc[0][0] += bv.x * a.x; acc[0][1] += bv.x * a.y; acc[0][2] += bv.x * a.z; acc[0][3] += bv.x * a.w;
        acc[1][0] += bv.y * a.x; acc[1][1] += bv.y * a.y; acc[1][2] += bv.y * a.z; acc[1][3] += bv.y * a.w;
        acc[2][0] += bv.z * a.x; acc[2][1] += bv.z * a.y; acc[2][2] += bv.z * a.z; acc[2][3] += bv.z * a.w;
        acc[3][0] += bv.w * a.x; acc[3][1] += bv.w * a.y; acc[3][2] += bv.w * a.z; acc[3][3] += bv.w * a.w;
    }

    #pragma unroll
    for (int p = 0; p < 4; p++) {
        int n = n0 + (ty << 2) + p;
        float4 st;
        st.x = acc[p][0]; st.y = acc[p][1]; st.z = acc[p][2]; st.w = acc[p][3];
        *(float4*)(g_x2p + ((kc << 8) + n) * 512 + m0 + (tx << 2)) = st;
    }
}

// ---------------- per-column: sum K-partials (+resb), BN+relu, per-b mean pool ----------------
__global__ void kPool(const float* __restrict__ gamma, const float* __restrict__ beta,
                      const float* __restrict__ resb) {
    __shared__ float sP[8];
    __shared__ float rs[8], rss[8];
    __shared__ float sScale, sShift;
    int c = blockIdx.x;        // 0..495
    int tid = threadIdx.x;     // 256
    int lane = tid & 31, w = tid >> 5;
    if (tid < 8) sP[tid] = 0.0f;

    float v0, v1;
    if (c < CO) {
        v0 = g_featsT[c * 512 + tid];
        v1 = g_featsT[c * 512 + 256 + tid];
    } else {
        int c2 = c - CO;
        float bb = resb[c2];
        v0 = bb; v1 = bb;
        #pragma unroll
        for (int q = 0; q < 8; q++) {
            const float* row = g_x2p + ((q << 8) + c2) * 512;
            v0 += row[tid];
            v1 += row[256 + tid];
        }
        float s = v0 + v1, ss = v0 * v0 + v1 * v1;
        #pragma unroll
        for (int o = 16; o > 0; o >>= 1) {
            s  += __shfl_down_sync(0xffffffffu, s, o);
            ss += __shfl_down_sync(0xffffffffu, ss, o);
        }
        if (lane == 0) { rs[w] = s; rss[w] = ss; }
        __syncthreads();
        if (tid == 0) {
            float S = 0.0f, SS = 0.0f;
            for (int q = 0; q < 8; q++) { S += rs[q]; SS += rss[q]; }
            float mu = S * (1.0f / 512.0f);
            float var = SS * (1.0f / 512.0f) - mu * mu;
            float sc = gamma[c2] * rsqrtf(var + 1e-5f);
            sScale = sc;
            sShift = beta[c2] - mu * sc;
        }
        __syncthreads();
        v0 = fmaxf(v0 * sScale + sShift, 0.0f);
        v1 = fmaxf(v1 * sScale + sShift, 0.0f);
    }
    __syncthreads();
    float p0 = v0, p1 = v1;
    #pragma unroll
    for (int o = 16; o > 0; o >>= 1) {
        p0 += __shfl_down_sync(0xffffffffu, p0, o);
        p1 += __shfl_down_sync(0xffffffffu, p1, o);
    }
    if (lane == 0) {
        atomicAdd(&sP[w >> 1], p0);
        atomicAdd(&sP[4 + (w >> 1)], p1);
    }
    __syncthreads();
    if (tid < 8) g_pooled[tid * RO + c] = sP[tid] * (1.0f / 64.0f);
}

// ---------------- head: h2 = leaky(pooled @ cW + cb); BN over batch; leaky; partials ----------------
__global__ void kHead(const float* __restrict__ cW, const float* __restrict__ cb,
                      const float* __restrict__ cg, const float* __restrict__ cbeta,
                      const float* __restrict__ oW) {
    __shared__ float sPart[8][8];
    __shared__ float sV[8];
    __shared__ float sMu, sIs;
    int ff = blockIdx.x;       // 128
    int tid = threadIdx.x;     // 256
    int lane = tid & 31, w = tid >> 5;
    float p[8];
    #pragma unroll
    for (int q = 0; q < 8; q++) p[q] = 0.0f;
    for (int c = tid; c < RO; c += 256) {
        float wv = cW[c * FFW + ff];
        #pragma unroll
        for (int q = 0; q < 8; q++) p[q] += g_pooled[q * RO + c] * wv;
    }
    #pragma unroll
    for (int q = 0; q < 8; q++) {
        #pragma unroll
        for (int o = 16; o > 0; o >>= 1) p[q] += __shfl_down_sync(0xffffffffu, p[q], o);
    }
    if (lane == 0) {
        #pragma unroll
        for (int q = 0; q < 8; q++) sPart[q][w] = p[q];
    }
    __syncthreads();
    if (tid < 8) {
        float h = cb[ff];
        for (int q = 0; q < 8; q++) h += sPart[tid][q];
        sV[tid] = (h > 0.0f) ? h : 0.01f * h;
    }
    __syncthreads();
    if (tid == 0) {
        float S = 0.0f, SS = 0.0f;
        for (int q = 0; q < 8; q++) { S += sV[q]; SS += sV[q] * sV[q]; }
        float mu = S * 0.125f;
        sMu = mu;
        sIs = rsqrtf(SS * 0.125f - mu * mu + 1e-5f);
    }
    __syncthreads();
    if (tid < 8) {
        float v = (sV[tid] - sMu) * sIs * cg[ff] + cbeta[ff];
        v = (v > 0.0f) ? v : 0.01f * v;
        g_hpart[tid * FFW + ff] = v * oW[ff];
    }
}

// ---------------- final reduce + sigmoid ----------------
__global__ void kOut(float* __restrict__ out, const float* __restrict__ ob) {
    int tid = threadIdx.x;     // 256
    int b = tid >> 5, lane = tid & 31;
    float s = g_hpart[b * FFW + lane] + g_hpart[b * FFW + 32 + lane]
            + g_hpart[b * FFW + 64 + lane] + g_hpart[b * FFW + 96 + lane];
    #pragma unroll
    for (int o = 16; o > 0; o >>= 1) s += __shfl_down_sync(0xffffffffu, s, o);
    if (lane == 0) out[b] = 1.0f / (1.0f + __expf(-(s + ob[0])));
}

extern "C" void kernel_launch(void* const* d_in, const int* in_sizes, int n_in,
                              void* d_out, int out_size) {
    const float* xyz   = (const float*)d_in[0];
    const int*   feat  = (const int*)  d_in[1];
    const float* emb   = (const float*)d_in[2];
    const float* rW1   = (const float*)d_in[3];
    const float* rb1   = (const float*)d_in[4];
    const float* rW2   = (const float*)d_in[5];
    const float* rb2   = (const float*)d_in[6];
    const float* rW3   = (const float*)d_in[7];
    const float* rb3   = (const float*)d_in[8];
    const float* resW  = (const float*)d_in[9];
    const float* resb  = (const float*)d_in[10];
    const float* resg  = (const float*)d_in[11];
    const float* resbe = (const float*)d_in[12];
    const float* cW    = (const float*)d_in[13];
    const float* cb    = (const float*)d_in[14];
    const float* cg    = (const float*)d_in[15];
    const float* cbe   = (const float*)d_in[16];
    const float* oW    = (const float*)d_in[17];
    const float* ob    = (const float*)d_in[18];
    float* out = (float*)d_out;

    cudaFuncSetAttribute(kTtab, cudaFuncAttributeMaxDynamicSharedMemorySize, TT_SMEM);

    kWfe<<<606, 128>>>(rW3, rb3, emb);
    kH2tab<<<128, 256>>>(rW1, rb1, rW2, rb2);
    kTtab<<<96, 256, TT_SMEM>>>();
    kGather<<<512, 512>>>(xyz, feat, emb);
    kRes<<<256, 256>>>(resW);
    kPool<<<496, 256>>>(resg, resbe, resb);
    kHead<<<128, 256>>>(cW, cb, cg, cbe, oW);
    kOut<<<1, 256>>>(out, ob);
}

// round 12
// speedup vs baseline: 1.2242x; 1.0531x over previous
#include <cuda_runtime.h>
#include <math.h>

#define BB   8
#define NN   64
#define CO   248
#define RO   496
#define FFW  128
#define TABN 256

// -------- device scratch --------
__device__ float g_Wfe[6 * 101 * 80];          // contracted radial weights per embedding (pad lu->80)
__device__ float g_H2T[100 * TABN];            // h2 table transposed [k][d]
__device__ __align__(16) float g_T[6 * TABN * 72];   // t table [e][d][72]
__device__ float g_featsT[CO * BB * NN];       // feats [248][512]
__device__ float g_x2p[8 * 256 * 512];         // residual GEMM partials [kc][n pad 256][m]
__device__ float g_pooled[BB * RO];
__device__ float g_hpart[BB * FFW];            // head partials

__device__ __forceinline__ float sp5(float x) {
    float z = 5.0f * x;
    return 0.2f * (fmaxf(z, 0.0f) + __logf(1.0f + __expf(-fabsf(z))));
}

// ---------------- Wfe[e][k][lu] = sum_v rW3[k, lu*32+v] * emb[e,v] / sqrt(32); row 100 = rb3 ----------------
// one block per kk (101 blocks); computes all 6 embeddings from one staged row
__global__ void __launch_bounds__(256) kWfe(const float* __restrict__ rW3,
                                            const float* __restrict__ rb3,
                                            const float* __restrict__ emb) {
    __shared__ float sRowT[32 * 73];
    __shared__ float sEmb[6 * 32];
    int kk = blockIdx.x;
    int tid = threadIdx.x;  // 256
    const float* src = (kk < 100) ? (rW3 + kk * 2304) : rb3;
    for (int idx = tid; idx < 2304; idx += 256) {
        int lu = idx >> 5, v = idx & 31;
        sRowT[v * 73 + lu] = src[idx];
    }
    if (tid < 192) sEmb[tid] = emb[tid];
    __syncthreads();
    for (int o = tid; o < 480; o += 256) {
        int e = o / 80, t = o - e * 80;
        float out = 0.0f;
        if (t < 72) {
            float acc = 0.0f;
            #pragma unroll
            for (int v = 0; v < 32; v++) acc += sRowT[v * 73 + t] * sEmb[e * 32 + v];
            out = acc * 0.17677669529663687f;
        }
        g_Wfe[e * 8080 + kk * 80 + t] = out;
    }
}

// ---------------- radial MLP table: H2T[k][d] over TABN d-samples in [0,2] ----------------
__global__ void __launch_bounds__(256) kH2tab(
    const float* __restrict__ rW1, const float* __restrict__ rb1,
    const float* __restrict__ rW2, const float* __restrict__ rb2) {
    __shared__ float sW2[10000];
    __shared__ float sh1[800];   // [k][s]
    __shared__ float sBa[24];    // [r][s]
    const int tid = threadIdx.x;
    const int d0 = blockIdx.x * 8;   // 32 blocks
    for (int idx = tid; idx < 10000; idx += 256) sW2[idx] = rW2[idx];
    if (tid < 24) {
        int s = tid & 7, r = tid >> 3;
        float d = (float)(d0 + s) * (2.0f / (float)(TABN - 1));
        float uu = fabsf(d - (float)r);
        float c = __cosf(1.57079632679f * uu);
        sBa[r * 8 + s] = (uu < 1.0f) ? c * c : 0.0f;
    }
    __syncthreads();
    for (int idx = tid; idx < 800; idx += 256) {
        int s = idx & 7, k = idx >> 3;
        float z = rb1[k] + sBa[s] * rW1[k] + sBa[8 + s] * rW1[100 + k] + sBa[16 + s] * rW1[200 + k];
        sh1[k * 8 + s] = sp5(z);
    }
    __syncthreads();
    for (int idx = tid; idx < 800; idx += 256) {
        int s = idx / 100, k2 = idx - s * 100;
        float acc = rb2[k2];
        #pragma unroll 4
        for (int k1 = 0; k1 < 100; k1++) acc += sh1[k1 * 8 + s] * sW2[k1 * 100 + k2];
        g_H2T[k2 * TABN + d0 + s] = sp5(acc);
    }
}

// ---------------- T[e][d][lu] = H2[d] @ Wfe[e] + bias ----------------
#define TT_SMEM ((8080 + 6400) * 4)
__global__ void __launch_bounds__(256) kTtab() {
    extern __shared__ float sm[];
    float* sWf = sm;           // 8080
    float* sA  = sm + 8080;    // [k][dd] 100*64
    const int tid = threadIdx.x;
    const int e = blockIdx.x >> 2, d0 = (blockIdx.x & 3) * 64;   // 24 blocks
    {
        const float4* srcW = (const float4*)(g_Wfe + e * 8080);
        float4* dstW = (float4*)sWf;
        for (int idx = tid; idx < 2020; idx += 256) dstW[idx] = srcW[idx];
    }
    for (int idx = tid; idx < 6400; idx += 256) {
        int k = idx >> 6, dd = idx & 63;
        sA[idx] = g_H2T[k * TABN + d0 + dd];
    }
    __syncthreads();
    const int dg = tid >> 4, lg = tid & 15;
    const int dd0 = dg << 2, lu0 = lg * 5;
    float a0[5], a1[5], a2[5], a3[5];
    #pragma unroll
    for (int t = 0; t < 5; t++) {
        float bb = sWf[8000 + lu0 + t];
        a0[t] = bb; a1[t] = bb; a2[t] = bb; a3[t] = bb;
    }
    #pragma unroll 2
    for (int k = 0; k < 100; k++) {
        float4 a = *(const float4*)(sA + (k << 6) + dd0);
        const float* wr = sWf + k * 80 + lu0;
        #pragma unroll
        for (int t = 0; t < 5; t++) {
            float w = wr[t];
            a0[t] += a.x * w; a1[t] += a.y * w; a2[t] += a.z * w; a3[t] += a.w * w;
        }
    }
    #pragma unroll
    for (int t = 0; t < 5; t++) {
        int lu = lu0 + t;
        if (lu < 72) {
            g_T[(e * TABN + d0 + dd0 + 0) * 72 + lu] = a0[t];
            g_T[(e * TABN + d0 + dd0 + 1) * 72 + lu] = a1[t];
            g_T[(e * TABN + d0 + dd0 + 2) * 72 + lu] = a2[t];
            g_T[(e * TABN + d0 + dd0 + 3) * 72 + lu] = a3[t];
        }
    }
}

// ---------------- gather: per (b,i): lerp-combined T rows, contract with mask*Y ----------------
__global__ void __launch_bounds__(512) kGather(const float* __restrict__ xyz,
                                               const int* __restrict__ feat,
                                               const float* __restrict__ emb) {
    __shared__ float sTl[64 * 72];    // lerp-combined T row per neighbor (18 KB)
    __shared__ float sY[64 * 12];     // mask*Y per neighbor
    __shared__ float sF2[64 * 2];     // lerp weights (1-f, f)
    __shared__ int   sBase[64];
    __shared__ float sPar[216];       // jj-half partials
    __shared__ float sMsum[2];
    __shared__ float sInv;
    const int bi = blockIdx.x;
    const int b = bi >> 6, i = bi & 63;
    const int tid = threadIdx.x;  // 512
    if (tid < 64) {
        int jj = tid;
        float dx = xyz[(b * 64 + jj) * 3 + 0] - xyz[bi * 3 + 0];
        float dy = xyz[(b * 64 + jj) * 3 + 1] - xyz[bi * 3 + 1];
        float dz = xyz[(b * 64 + jj) * 3 + 2] - xyz[bi * 3 + 2];
        float d = sqrtf(dx * dx + dy * dy + dz * dz + 1e-8f);
        float m = (d < 2.0f && jj != i) ? 1.0f : 0.0f;
        float inv = 1.0f / d;
        float ux = dx * inv, uy = dy * inv, uz = dz * inv;
        float db = d * ((float)(TABN - 1) * 0.5f);
        int bin = (int)db;
        bin = (bin > TABN - 2) ? (TABN - 2) : bin;
        float f = db - (float)bin;
        sBase[jj] = (feat[b * 64 + jj] * TABN + bin) * 72;
        sF2[2 * jj]     = 1.0f - f;
        sF2[2 * jj + 1] = f;
        float* yr = sY + jj * 12;
        yr[0] = m * 0.28209479177f;
        yr[1] = m * 0.48860251190f * uy;
        yr[2] = m * 0.48860251190f * uz;
        yr[3] = m * 0.48860251190f * ux;
        yr[4] = m * 1.09254843059f * ux * uy;
        yr[5] = m * 1.09254843059f * uy * uz;
        yr[6] = m * 0.31539156525f * (3.0f * uz * uz - 1.0f);
        yr[7] = m * 1.09254843059f * ux * uz;
        yr[8] = m * 0.54627421529f * (ux * ux - uy * uy);
        float s = m;
        #pragma unroll
        for (int o = 16; o > 0; o >>= 1) s += __shfl_down_sync(0xffffffffu, s, o);
        if ((tid & 31) == 0) sMsum[tid >> 5] = s;
    }
    __syncthreads();
    if (tid == 0) sInv = rsqrtf(fmaxf(sMsum[0] + sMsum[1], 1.0f));
    // staging + lerp: 8 threads per neighbor; rows bin/bin+1 are adjacent (stride 18 float4)
    {
        const int jj = tid >> 3, seg = tid & 7;
        const float4* r1 = (const float4*)(g_T + sBase[jj]);
        const float f1 = sF2[2 * jj], f2 = sF2[2 * jj + 1];
        float4* dst = (float4*)(sTl + jj * 72);
        #pragma unroll
        for (int q = seg; q < 18; q += 8) {
            float4 a = r1[q], c = r1[q + 18];
            float4 o;
            o.x = f1 * a.x + f2 * c.x;
            o.y = f1 * a.y + f2 * c.y;
            o.z = f1 * a.z + f2 * c.z;
            o.w = f1 * a.w + f2 * c.w;
            dst[q] = o;
        }
    }
    __syncthreads();
    // contraction: 216 channels x 2 jj-halves
    {
        int ch = -1, jj0 = 0;
        if (tid < 216)                       { ch = tid;       jj0 = 0;  }
        else if (tid >= 256 && tid < 472)    { ch = tid - 256; jj0 = 32; }
        float acc = 0.0f;
        int lu = 0, ym = 0;
        if (ch >= 0) {
            if (ch < 24)      { lu = ch; ym = 0; }
            else if (ch < 96) { int q = ch - 24; int u = q / 3; ym = 1 + (q - u * 3); lu = 24 + u; }
            else              { int q = ch - 96; int u = q / 5; ym = 4 + (q - u * 5); lu = 48 + u; }
            #pragma unroll 8
            for (int jj = jj0; jj < jj0 + 32; jj++)
                acc += sY[jj * 12 + ym] * sTl[jj * 72 + lu];
            if (jj0 == 32) sPar[ch] = acc;
        }
        __syncthreads();
        if (ch >= 0 && jj0 == 0)
            g_featsT[(32 + ch) * 512 + bi] = (acc + sPar[ch]) * sInv;
        else if (tid >= 216 && tid < 248) {
            int c = tid - 216;
            g_featsT[c * 512 + bi] = emb[feat[bi] * 32 + c];
        }
    }
}

// ---------------- residual GEMM, K-split: 32 tiles (64m x 64n) x 8 K-chunks of 31 ----------------
__global__ void __launch_bounds__(256) kRes(const float* __restrict__ resW) {
    __shared__ float sA[31 * 64];   // featsT chunk [k][m]
    __shared__ float sB[31 * 64];   // resW  chunk [k][n]
    const int tid = threadIdx.x;
    const int tile = blockIdx.x & 31;
    const int kc   = blockIdx.x >> 5;
    const int m0 = (tile & 7) * 64;
    const int n0 = (tile >> 3) * 64;
    const int kb = kc * 31;
    const int tx = tid & 15, ty = tid >> 4;

    for (int idx = tid; idx < 1984; idx += 256) {
        int r = idx >> 6, mm = idx & 63;
        sA[idx] = g_featsT[(kb + r) * 512 + m0 + mm];
        int n = n0 + mm;
        sB[idx] = (n < CO) ? resW[(kb + r) * CO + n] : 0.0f;
    }
    __syncthreads();

    float acc[4][4];
    #pragma unroll
    for (int p = 0; p < 4; p++)
        #pragma unroll
        for (int q = 0; q < 4; q++) acc[p][q] = 0.0f;

    #pragma unroll
    for (int r = 0; r < 31; r++) {
        float4 a  = *(const float4*)(sA + (r << 6) + (tx << 2));
        float4 bv = *(const float4*)(sB + (r << 6) + (ty << 2));
        acc[0][0] += bv.x * a.x; acc[0][1] += bv.x * a.y; acc[0][2] += bv.x * a.z; acc[0][3] += bv.x * a.w;
        acc[1][0] += bv.y * a.x; acc[1][1] += bv.y * a.y; acc[1][2] += bv.y * a.z; acc[1][3] += bv.y * a.w;
        acc[2][0] += bv.z * a.x; acc[2][1] += bv.z * a.y; acc[2][2] += bv.z * a.z; acc[2][3] += bv.z * a.w;
        acc[3][0] += bv.w * a.x; acc[3][1] += bv.w * a.y; acc[3][2] += bv.w * a.z; acc[3][3] += bv.w * a.w;
    }

    #pragma unroll
    for (int p = 0; p < 4; p++) {
        int n = n0 + (ty << 2) + p;
        float4 st;
        st.x = acc[p][0]; st.y = acc[p][1]; st.z = acc[p][2]; st.w = acc[p][3];
        *(float4*)(g_x2p + ((kc << 8) + n) * 512 + m0 + (tx << 2)) = st;
    }
}

// ---------------- per-column: sum K-partials (+resb), BN+relu, per-b mean pool ----------------
__global__ void kPool(const float* __restrict__ gamma, const float* __restrict__ beta,
                      const float* __restrict__ resb) {
    __shared__ float sP[8];
    __shared__ float rs[8], rss[8];
    __shared__ float sScale, sShift;
    int c = blockIdx.x;        // 0..495
    int tid = threadIdx.x;     // 256
    int lane = tid & 31, w = tid >> 5;
    if (tid < 8) sP[tid] = 0.0f;

    float v0, v1;
    if (c < CO) {
        v0 = g_featsT[c * 512 + tid];
        v1 = g_featsT[c * 512 + 256 + tid];
    } else {
        int c2 = c - CO;
        float bb = resb[c2];
        v0 = bb; v1 = bb;
        #pragma unroll
        for (int q = 0; q < 8; q++) {
            const float* row = g_x2p + ((q << 8) + c2) * 512;
            v0 += row[tid];
            v1 += row[256 + tid];
        }
        float s = v0 + v1, ss = v0 * v0 + v1 * v1;
        #pragma unroll
        for (int o = 16; o > 0; o >>= 1) {
            s  += __shfl_down_sync(0xffffffffu, s, o);
            ss += __shfl_down_sync(0xffffffffu, ss, o);
        }
        if (lane == 0) { rs[w] = s; rss[w] = ss; }
        __syncthreads();
        if (tid == 0) {
            float S = 0.0f, SS = 0.0f;
            for (int q = 0; q < 8; q++) { S += rs[q]; SS += rss[q]; }
            float mu = S * (1.0f / 512.0f);
            float var = SS * (1.0f / 512.0f) - mu * mu;
            float sc = gamma[c2] * rsqrtf(var + 1e-5f);
            sScale = sc;
            sShift = beta[c2] - mu * sc;
        }
        __syncthreads();
        v0 = fmaxf(v0 * sScale + sShift, 0.0f);
        v1 = fmaxf(v1 * sScale + sShift, 0.0f);
    }
    __syncthreads();
    float p0 = v0, p1 = v1;
    #pragma unroll
    for (int o = 16; o > 0; o >>= 1) {
        p0 += __shfl_down_sync(0xffffffffu, p0, o);
        p1 += __shfl_down_sync(0xffffffffu, p1, o);
    }
    if (lane == 0) {
        atomicAdd(&sP[w >> 1], p0);
        atomicAdd(&sP[4 + (w >> 1)], p1);
    }
    __syncthreads();
    if (tid < 8) g_pooled[tid * RO + c] = sP[tid] * (1.0f / 64.0f);
}

// ---------------- head: h2 = leaky(pooled @ cW + cb); BN over batch; leaky; partials ----------------
__global__ void kHead(const float* __restrict__ cW, const float* __restrict__ cb,
                      const float* __restrict__ cg, const float* __restrict__ cbeta,
                      const float* __restrict__ oW) {
    __shared__ float sPart[8][8];
    __shared__ float sV[8];
    __shared__ float sMu, sIs;
    int ff = blockIdx.x;       // 128
    int tid = threadIdx.x;     // 256
    int lane = tid & 31, w = tid >> 5;
    float p[8];
    #pragma unroll
    for (int q = 0; q < 8; q++) p[q] = 0.0f;
    for (int c = tid; c < RO; c += 256) {
        float wv = cW[c * FFW + ff];
        #pragma unroll
        for (int q = 0; q < 8; q++) p[q] += g_pooled[q * RO + c] * wv;
    }
    #pragma unroll
    for (int q = 0; q < 8; q++) {
        #pragma unroll
        for (int o = 16; o > 0; o >>= 1) p[q] += __shfl_down_sync(0xffffffffu, p[q], o);
    }
    if (lane == 0) {
        #pragma unroll
        for (int q = 0; q < 8; q++) sPart[q][w] = p[q];
    }
    __syncthreads();
    if (tid < 8) {
        float h = cb[ff];
        for (int q = 0; q < 8; q++) h += sPart[tid][q];
        sV[tid] = (h > 0.0f) ? h : 0.01f * h;
    }
    __syncthreads();
    if (tid == 0) {
        float S = 0.0f, SS = 0.0f;
        for (int q = 0; q < 8; q++) { S += sV[q]; SS += sV[q] * sV[q]; }
        float mu = S * 0.125f;
        sMu = mu;
        sIs = rsqrtf(SS * 0.125f - mu * mu + 1e-5f);
    }
    __syncthreads();
    if (tid < 8) {
        float v = (sV[tid] - sMu) * sIs * cg[ff] + cbeta[ff];
        v = (v > 0.0f) ? v : 0.01f * v;
        g_hpart[tid * FFW + ff] = v * oW[ff];
    }
}

// ---------------- final reduce + sigmoid ----------------
__global__ void kOut(float* __restrict__ out, const float* __restrict__ ob) {
    int tid = threadIdx.x;     // 256
    int b = tid >> 5, lane = tid & 31;
    float s = g_hpart[b * FFW + lane] + g_hpart[b * FFW + 32 + lane]
            + g_hpart[b * FFW + 64 + lane] + g_hpart[b * FFW + 96 + lane];
    #pragma unroll
    for (int o = 16; o > 0; o >>= 1) s += __shfl_down_sync(0xffffffffu, s, o);
    if (lane == 0) out[b] = 1.0f / (1.0f + __expf(-(s + ob[0])));
}

extern "C" void kernel_launch(void* const* d_in, const int* in_sizes, int n_in,
                              void* d_out, int out_size) {
    const float* xyz   = (const float*)d_in[0];
    const int*   feat  = (const int*)  d_in[1];
    const float* emb   = (const float*)d_in[2];
    const float* rW1   = (const float*)d_in[3];
    const float* rb1   = (const float*)d_in[4];
    const float* rW2   = (const float*)d_in[5];
    const float* rb2   = (const float*)d_in[6];
    const float* rW3   = (const float*)d_in[7];
    const float* rb3   = (const float*)d_in[8];
    const float* resW  = (const float*)d_in[9];
    const float* resb  = (const float*)d_in[10];
    const float* resg  = (const float*)d_in[11];
    const float* resbe = (const float*)d_in[12];
    const float* cW    = (const float*)d_in[13];
    const float* cb    = (const float*)d_in[14];
    const float* cg    = (const float*)d_in[15];
    const float* cbe   = (const float*)d_in[16];
    const float* oW    = (const float*)d_in[17];
    const float* ob    = (const float*)d_in[18];
    float* out = (float*)d_out;

    cudaFuncSetAttribute(kTtab, cudaFuncAttributeMaxDynamicSharedMemorySize, TT_SMEM);

    kWfe<<<101, 256>>>(rW3, rb3, emb);
    kH2tab<<<TABN / 8, 256>>>(rW1, rb1, rW2, rb2);
    kTtab<<<6 * (TABN / 64), 256, TT_SMEM>>>();
    kGather<<<512, 512>>>(xyz, feat, emb);
    kRes<<<256, 256>>>(resW);
    kPool<<<496, 256>>>(resg, resbe, resb);
    kHead<<<128, 256>>>(cW, cb, cg, cbe, oW);
    kOut<<<1, 256>>>(out, ob);
}

// round 13
// speedup vs baseline: 1.3141x; 1.0735x over previous
#include <cuda_runtime.h>
#include <math.h>

#define BB   8
#define NN   64
#define CO   248
#define RO   496
#define FFW  128
#define TABN 256

// -------- device scratch --------
__device__ float g_Wfe[6 * 101 * 80];          // contracted radial weights per embedding (pad lu->80)
__device__ float g_H2T[100 * TABN];            // h2 table transposed [k][d]
__device__ __align__(16) float g_T[6 * TABN * 72];   // t table [e][d][72]
__device__ float g_featsT[CO * BB * NN];       // feats [248][512]
__device__ float g_x2p[8 * 256 * 512];         // residual GEMM partials [kc][n pad 256][m]
__device__ float g_pooled[BB * RO];
__device__ float g_hpart[BB * FFW];            // head partials
__device__ unsigned int g_cnt;                 // last-block counter (self-resetting)

__device__ __forceinline__ float sp5(float x) {
    float z = 5.0f * x;
    return 0.2f * (fmaxf(z, 0.0f) + __logf(1.0f + __expf(-fabsf(z))));
}

// ---------------- fused prep: blocks [0,101) = Wfe, [101,133) = radial MLP table ----------------
// 133 blocks <= 148 SMs -> single wave; fat smem cannot cost a wave.
__global__ void __launch_bounds__(256) kPrep(
    const float* __restrict__ rW3, const float* __restrict__ rb3,
    const float* __restrict__ emb,
    const float* __restrict__ rW1, const float* __restrict__ rb1,
    const float* __restrict__ rW2, const float* __restrict__ rb2) {
    __shared__ float smem[11648];   // 46592 B
    const int tid = threadIdx.x;
    if (blockIdx.x < 101) {
        // ---- Wfe: one block per kk; all 6 embeddings from one staged row ----
        float* sRowT = smem;            // 32*73
        float* sEmb  = smem + 2336;     // 192
        int kk = blockIdx.x;
        const float* src = (kk < 100) ? (rW3 + kk * 2304) : rb3;
        for (int idx = tid; idx < 2304; idx += 256) {
            int lu = idx >> 5, v = idx & 31;
            sRowT[v * 73 + lu] = src[idx];
        }
        if (tid < 192) sEmb[tid] = emb[tid];
        __syncthreads();
        for (int o = tid; o < 480; o += 256) {
            int e = o / 80, t = o - e * 80;
            float out = 0.0f;
            if (t < 72) {
                float acc = 0.0f;
                #pragma unroll
                for (int v = 0; v < 32; v++) acc += sRowT[v * 73 + t] * sEmb[e * 32 + v];
                out = acc * 0.17677669529663687f;
            }
            g_Wfe[e * 8080 + kk * 80 + t] = out;
        }
    } else {
        // ---- H2 table: 8 d-samples per block ----
        float* sW2 = smem;              // 10000
        float* sh1 = smem + 10000;      // 800
        float* sBa = smem + 10800;      // 24
        const int d0 = (blockIdx.x - 101) * 8;
        for (int idx = tid; idx < 10000; idx += 256) sW2[idx] = rW2[idx];
        if (tid < 24) {
            int s = tid & 7, r = tid >> 3;
            float d = (float)(d0 + s) * (2.0f / (float)(TABN - 1));
            float uu = fabsf(d - (float)r);
            float c = __cosf(1.57079632679f * uu);
            sBa[r * 8 + s] = (uu < 1.0f) ? c * c : 0.0f;
        }
        __syncthreads();
        for (int idx = tid; idx < 800; idx += 256) {
            int s = idx & 7, k = idx >> 3;
            float z = rb1[k] + sBa[s] * rW1[k] + sBa[8 + s] * rW1[100 + k] + sBa[16 + s] * rW1[200 + k];
            sh1[k * 8 + s] = sp5(z);
        }
        __syncthreads();
        for (int idx = tid; idx < 800; idx += 256) {
            int s = idx / 100, k2 = idx - s * 100;
            float acc = rb2[k2];
            #pragma unroll 4
            for (int k1 = 0; k1 < 100; k1++) acc += sh1[k1 * 8 + s] * sW2[k1 * 100 + k2];
            g_H2T[k2 * TABN + d0 + s] = sp5(acc);
        }
    }
}

// ---------------- T[e][d][lu] = H2[d] @ Wfe[e] + bias ----------------
#define TT_SMEM ((8080 + 6400) * 4)
__global__ void __launch_bounds__(256) kTtab() {
    extern __shared__ float sm[];
    float* sWf = sm;           // 8080
    float* sA  = sm + 8080;    // [k][dd] 100*64
    const int tid = threadIdx.x;
    const int e = blockIdx.x >> 2, d0 = (blockIdx.x & 3) * 64;   // 24 blocks
    {
        const float4* srcW = (const float4*)(g_Wfe + e * 8080);
        float4* dstW = (float4*)sWf;
        for (int idx = tid; idx < 2020; idx += 256) dstW[idx] = srcW[idx];
    }
    for (int idx = tid; idx < 6400; idx += 256) {
        int k = idx >> 6, dd = idx & 63;
        sA[idx] = g_H2T[k * TABN + d0 + dd];
    }
    __syncthreads();
    const int dg = tid >> 4, lg = tid & 15;
    const int dd0 = dg << 2, lu0 = lg * 5;
    float a0[5], a1[5], a2[5], a3[5];
    #pragma unroll
    for (int t = 0; t < 5; t++) {
        float bb = sWf[8000 + lu0 + t];
        a0[t] = bb; a1[t] = bb; a2[t] = bb; a3[t] = bb;
    }
    #pragma unroll 2
    for (int k = 0; k < 100; k++) {
        float4 a = *(const float4*)(sA + (k << 6) + dd0);
        const float* wr = sWf + k * 80 + lu0;
        #pragma unroll
        for (int t = 0; t < 5; t++) {
            float w = wr[t];
            a0[t] += a.x * w; a1[t] += a.y * w; a2[t] += a.z * w; a3[t] += a.w * w;
        }
    }
    #pragma unroll
    for (int t = 0; t < 5; t++) {
        int lu = lu0 + t;
        if (lu < 72) {
            g_T[(e * TABN + d0 + dd0 + 0) * 72 + lu] = a0[t];
            g_T[(e * TABN + d0 + dd0 + 1) * 72 + lu] = a1[t];
            g_T[(e * TABN + d0 + dd0 + 2) * 72 + lu] = a2[t];
            g_T[(e * TABN + d0 + dd0 + 3) * 72 + lu] = a3[t];
        }
    }
}

// ---------------- gather: per (b,i): lerp-combined T rows, contract with mask*Y ----------------
__global__ void __launch_bounds__(512) kGather(const float* __restrict__ xyz,
                                               const int* __restrict__ feat,
                                               const float* __restrict__ emb) {
    __shared__ float sTl[64 * 72];    // lerp-combined T row per neighbor (18 KB)
    __shared__ float sY[64 * 12];     // mask*Y per neighbor
    __shared__ float sF2[64 * 2];     // lerp weights (1-f, f)
    __shared__ int   sBase[64];
    __shared__ float sPar[216];       // jj-half partials
    __shared__ float sMsum[2];
    __shared__ float sInv;
    const int bi = blockIdx.x;
    const int b = bi >> 6, i = bi & 63;
    const int tid = threadIdx.x;  // 512
    if (tid < 64) {
        int jj = tid;
        float dx = xyz[(b * 64 + jj) * 3 + 0] - xyz[bi * 3 + 0];
        float dy = xyz[(b * 64 + jj) * 3 + 1] - xyz[bi * 3 + 1];
        float dz = xyz[(b * 64 + jj) * 3 + 2] - xyz[bi * 3 + 2];
        float d = sqrtf(dx * dx + dy * dy + dz * dz + 1e-8f);
        float m = (d < 2.0f && jj != i) ? 1.0f : 0.0f;
        float inv = 1.0f / d;
        float ux = dx * inv, uy = dy * inv, uz = dz * inv;
        float db = d * ((float)(TABN - 1) * 0.5f);
        int bin = (int)db;
        bin = (bin > TABN - 2) ? (TABN - 2) : bin;
        float f = db - (float)bin;
        sBase[jj] = (feat[b * 64 + jj] * TABN + bin) * 72;
        sF2[2 * jj]     = 1.0f - f;
        sF2[2 * jj + 1] = f;
        float* yr = sY + jj * 12;
        yr[0] = m * 0.28209479177f;
        yr[1] = m * 0.48860251190f * uy;
        yr[2] = m * 0.48860251190f * uz;
        yr[3] = m * 0.48860251190f * ux;
        yr[4] = m * 1.09254843059f * ux * uy;
        yr[5] = m * 1.09254843059f * uy * uz;
        yr[6] = m * 0.31539156525f * (3.0f * uz * uz - 1.0f);
        yr[7] = m * 1.09254843059f * ux * uz;
        yr[8] = m * 0.54627421529f * (ux * ux - uy * uy);
        float s = m;
        #pragma unroll
        for (int o = 16; o > 0; o >>= 1) s += __shfl_down_sync(0xffffffffu, s, o);
        if ((tid & 31) == 0) sMsum[tid >> 5] = s;
    }
    __syncthreads();
    if (tid == 0) sInv = rsqrtf(fmaxf(sMsum[0] + sMsum[1], 1.0f));
    // staging + lerp: 8 threads per neighbor; rows bin/bin+1 are adjacent (stride 18 float4)
    {
        const int jj = tid >> 3, seg = tid & 7;
        const float4* r1 = (const float4*)(g_T + sBase[jj]);
        const float f1 = sF2[2 * jj], f2 = sF2[2 * jj + 1];
        float4* dst = (float4*)(sTl + jj * 72);
        #pragma unroll
        for (int q = seg; q < 18; q += 8) {
            float4 a = r1[q], c = r1[q + 18];
            float4 o;
            o.x = f1 * a.x + f2 * c.x;
            o.y = f1 * a.y + f2 * c.y;
            o.z = f1 * a.z + f2 * c.z;
            o.w = f1 * a.w + f2 * c.w;
            dst[q] = o;
        }
    }
    __syncthreads();
    // contraction: 216 channels x 2 jj-halves
    {
        int ch = -1, jj0 = 0;
        if (tid < 216)                       { ch = tid;       jj0 = 0;  }
        else if (tid >= 256 && tid < 472)    { ch = tid - 256; jj0 = 32; }
        float acc = 0.0f;
        int lu = 0, ym = 0;
        if (ch >= 0) {
            if (ch < 24)      { lu = ch; ym = 0; }
            else if (ch < 96) { int q = ch - 24; int u = q / 3; ym = 1 + (q - u * 3); lu = 24 + u; }
            else              { int q = ch - 96; int u = q / 5; ym = 4 + (q - u * 5); lu = 48 + u; }
            #pragma unroll 8
            for (int jj = jj0; jj < jj0 + 32; jj++)
                acc += sY[jj * 12 + ym] * sTl[jj * 72 + lu];
            if (jj0 == 32) sPar[ch] = acc;
        }
        __syncthreads();
        if (ch >= 0 && jj0 == 0)
            g_featsT[(32 + ch) * 512 + bi] = (acc + sPar[ch]) * sInv;
        else if (tid >= 216 && tid < 248) {
            int c = tid - 216;
            g_featsT[c * 512 + bi] = emb[feat[bi] * 32 + c];
        }
    }
}

// ---------------- residual GEMM, K-split: 32 tiles (64m x 64n) x 8 K-chunks of 31 ----------------
__global__ void __launch_bounds__(256) kRes(const float* __restrict__ resW) {
    __shared__ float sA[31 * 64];   // featsT chunk [k][m]
    __shared__ float sB[31 * 64];   // resW  chunk [k][n]
    const int tid = threadIdx.x;
    const int tile = blockIdx.x & 31;
    const int kc   = blockIdx.x >> 5;
    const int m0 = (tile & 7) * 64;
    const int n0 = (tile >> 3) * 64;
    const int kb = kc * 31;
    const int tx = tid & 15, ty = tid >> 4;

    for (int idx = tid; idx < 1984; idx += 256) {
        int r = idx >> 6, mm = idx & 63;
        sA[idx] = g_featsT[(kb + r) * 512 + m0 + mm];
        int n = n0 + mm;
        sB[idx] = (n < CO) ? resW[(kb + r) * CO + n] : 0.0f;
    }
    __syncthreads();

    float acc[4][4];
    #pragma unroll
    for (int p = 0; p < 4; p++)
        #pragma unroll
        for (int q = 0; q < 4; q++) acc[p][q] = 0.0f;

    #pragma unroll
    for (int r = 0; r < 31; r++) {
        float4 a  = *(const float4*)(sA + (r << 6) + (tx << 2));
        float4 bv = *(const float4*)(sB + (r << 6) + (ty << 2));
        acc[0][0] += bv.x * a.x; acc[0][1] += bv.x * a.y; acc[0][2] += bv.x * a.z; acc[0][3] += bv.x * a.w;
        acc[1][0] += bv.y * a.x; acc[1][1] += bv.y * a.y; acc[1][2] += bv.y * a.z; acc[1][3] += bv.y * a.w;
        acc[2][0] += bv.z * a.x; acc[2][1] += bv.z * a.y; acc[2][2] += bv.z * a.z; acc[2][3] += bv.z * a.w;
        acc[3][0] += bv.w * a.x; acc[3][1] += bv.w * a.y; acc[3][2] += bv.w * a.z; acc[3][3] += bv.w * a.w;
    }

    #pragma unroll
    for (int p = 0; p < 4; p++) {
        int n = n0 + (ty << 2) + p;
        float4 st;
        st.x = acc[p][0]; st.y = acc[p][1]; st.z = acc[p][2]; st.w = acc[p][3];
        *(float4*)(g_x2p + ((kc << 8) + n) * 512 + m0 + (tx << 2)) = st;
    }
}

// ---------------- per-column: sum K-partials (+resb), BN+relu, per-b mean pool ----------------
__global__ void kPool(const float* __restrict__ gamma, const float* __restrict__ beta,
                      const float* __restrict__ resb) {
    __shared__ float sP[8];
    __shared__ float rs[8], rss[8];
    __shared__ float sScale, sShift;
    int c = blockIdx.x;        // 0..495
    int tid = threadIdx.x;     // 256
    int lane = tid & 31, w = tid >> 5;
    if (tid < 8) sP[tid] = 0.0f;

    float v0, v1;
    if (c < CO) {
        v0 = g_featsT[c * 512 + tid];
        v1 = g_featsT[c * 512 + 256 + tid];
    } else {
        int c2 = c - CO;
        float bb = resb[c2];
        v0 = bb; v1 = bb;
        #pragma unroll
        for (int q = 0; q < 8; q++) {
            const float* row = g_x2p + ((q << 8) + c2) * 512;
            v0 += row[tid];
            v1 += row[256 + tid];
        }
        float s = v0 + v1, ss = v0 * v0 + v1 * v1;
        #pragma unroll
        for (int o = 16; o > 0; o >>= 1) {
            s  += __shfl_down_sync(0xffffffffu, s, o);
            ss += __shfl_down_sync(0xffffffffu, ss, o);
        }
        if (lane == 0) { rs[w] = s; rss[w] = ss; }
        __syncthreads();
        if (tid == 0) {
            float S = 0.0f, SS = 0.0f;
            for (int q = 0; q < 8; q++) { S += rs[q]; SS += rss[q]; }
            float mu = S * (1.0f / 512.0f);
            float var = SS * (1.0f / 512.0f) - mu * mu;
            float sc = gamma[c2] * rsqrtf(var + 1e-5f);
            sScale = sc;
            sShift = beta[c2] - mu * sc;
        }
        __syncthreads();
        v0 = fmaxf(v0 * sScale + sShift, 0.0f);
        v1 = fmaxf(v1 * sScale + sShift, 0.0f);
    }
    __syncthreads();
    float p0 = v0, p1 = v1;
    #pragma unroll
    for (int o = 16; o > 0; o >>= 1) {
        p0 += __shfl_down_sync(0xffffffffu, p0, o);
        p1 += __shfl_down_sync(0xffffffffu, p1, o);
    }
    if (lane == 0) {
        atomicAdd(&sP[w >> 1], p0);
        atomicAdd(&sP[4 + (w >> 1)], p1);
    }
    __syncthreads();
    if (tid < 8) g_pooled[tid * RO + c] = sP[tid] * (1.0f / 64.0f);
}

// ---------------- head + last-block output: h2 = leaky(pooled @ cW + cb); BN; leaky; reduce; sigmoid ----------------
__global__ void kHead(const float* __restrict__ cW, const float* __restrict__ cb,
                      const float* __restrict__ cg, const float* __restrict__ cbeta,
                      const float* __restrict__ oW, const float* __restrict__ ob,
                      float* __restrict__ out) {
    __shared__ float sPart[8][8];
    __shared__ float sV[8];
    __shared__ float sMu, sIs;
    __shared__ unsigned int sIsLast;
    int ff = blockIdx.x;       // 128
    int tid = threadIdx.x;     // 256
    int lane = tid & 31, w = tid >> 5;
    float p[8];
    #pragma unroll
    for (int q = 0; q < 8; q++) p[q] = 0.0f;
    for (int c = tid; c < RO; c += 256) {
        float wv = cW[c * FFW + ff];
        #pragma unroll
        for (int q = 0; q < 8; q++) p[q] += g_pooled[q * RO + c] * wv;
    }
    #pragma unroll
    for (int q = 0; q < 8; q++) {
        #pragma unroll
        for (int o = 16; o > 0; o >>= 1) p[q] += __shfl_down_sync(0xffffffffu, p[q], o);
    }
    if (lane == 0) {
        #pragma unroll
        for (int q = 0; q < 8; q++) sPart[q][w] = p[q];
    }
    __syncthreads();
    if (tid < 8) {
        float h = cb[ff];
        for (int q = 0; q < 8; q++) h += sPart[tid][q];
        sV[tid] = (h > 0.0f) ? h : 0.01f * h;
    }
    __syncthreads();
    if (tid == 0) {
        float S = 0.0f, SS = 0.0f;
        for (int q = 0; q < 8; q++) { S += sV[q]; SS += sV[q] * sV[q]; }
        float mu = S * 0.125f;
        sMu = mu;
        sIs = rsqrtf(SS * 0.125f - mu * mu + 1e-5f);
    }
    __syncthreads();
    if (tid < 8) {
        float v = (sV[tid] - sMu) * sIs * cg[ff] + cbeta[ff];
        v = (v > 0.0f) ? v : 0.01f * v;
        g_hpart[tid * FFW + ff] = v * oW[ff];
    }
    __syncthreads();
    // last-block reduce + sigmoid (counter self-resets via atomicInc wrap at 127)
    if (tid == 0) {
        __threadfence();
        sIsLast = (atomicInc(&g_cnt, 127) == 127) ? 1u : 0u;
    }
    __syncthreads();
    if (sIsLast) {
        __threadfence();   // acquire: make all blocks' g_hpart writes visible
        int bq = tid >> 5, ln = tid & 31;
        float s = g_hpart[bq * FFW + ln] + g_hpart[bq * FFW + 32 + ln]
                + g_hpart[bq * FFW + 64 + ln] + g_hpart[bq * FFW + 96 + ln];
        #pragma unroll
        for (int o = 16; o > 0; o >>= 1) s += __shfl_down_sync(0xffffffffu, s, o);
        if (ln == 0) out[bq] = 1.0f / (1.0f + __expf(-(s + ob[0])));
    }
}

extern "C" void kernel_launch(void* const* d_in, const int* in_sizes, int n_in,
                              void* d_out, int out_size) {
    const float* xyz   = (const float*)d_in[0];
    const int*   feat  = (const int*)  d_in[1];
    const float* emb   = (const float*)d_in[2];
    const float* rW1   = (const float*)d_in[3];
    const float* rb1   = (const float*)d_in[4];
    const float* rW2   = (const float*)d_in[5];
    const float* rb2   = (const float*)d_in[6];
    const float* rW3   = (const float*)d_in[7];
    const float* rb3   = (const float*)d_in[8];
    const float* resW  = (const float*)d_in[9];
    const float* resb  = (const float*)d_in[10];
    const float* resg  = (const float*)d_in[11];
    const float* resbe = (const float*)d_in[12];
    const float* cW    = (const float*)d_in[13];
    const float* cb    = (const float*)d_in[14];
    const float* cg    = (const float*)d_in[15];
    const float* cbe   = (const float*)d_in[16];
    const float* oW    = (const float*)d_in[17];
    const float* ob    = (const float*)d_in[18];
    float* out = (float*)d_out;

    cudaFuncSetAttribute(kTtab, cudaFuncAttributeMaxDynamicSharedMemorySize, TT_SMEM);

    kPrep<<<101 + TABN / 8, 256>>>(rW3, rb3, emb, rW1, rb1, rW2, rb2);
    kTtab<<<6 * (TABN / 64), 256, TT_SMEM>>>();
    kGather<<<512, 512>>>(xyz, feat, emb);
    kRes<<<256, 256>>>(resW);
    kPool<<<496, 256>>>(resg, resbe, resb);
    kHead<<<128, 256>>>(cW, cb, cg, cbe, oW, ob, out);
}

// round 14
// speedup vs baseline: 1.3537x; 1.0301x over previous
#include <cuda_runtime.h>
#include <math.h>

#define BB   8
#define NN   64
#define CO   248
#define RO   496
#define FFW  128
#define TABN 256

// -------- device scratch --------
__device__ float g_Wfe[6 * 101 * 80];          // contracted radial weights per embedding (pad lu->80)
__device__ float g_H2T[100 * TABN];            // h2 table transposed [k][d]
__device__ __align__(16) float g_T[6 * TABN * 72];   // t table [e][d][72]
__device__ float g_featsT[CO * BB * NN];       // feats [248][512]
__device__ float g_x2p[8 * 256 * 512];         // residual GEMM partials [kc][n pad 256][m]
__device__ float g_pooled[BB * RO];
__device__ float g_hpart[BB * FFW];            // head partials
__device__ unsigned int g_cnt;                 // last-block counter (self-resetting)

__device__ __forceinline__ float sp5(float x) {
    float z = 5.0f * x;
    return 0.2f * (fmaxf(z, 0.0f) + __logf(1.0f + __expf(-fabsf(z))));
}

// ---------------- fused prep: blocks [0,101) = Wfe, [101,133) = radial MLP table ----------------
__global__ void __launch_bounds__(256) kPrep(
    const float* __restrict__ rW3, const float* __restrict__ rb3,
    const float* __restrict__ emb,
    const float* __restrict__ rW1, const float* __restrict__ rb1,
    const float* __restrict__ rW2, const float* __restrict__ rb2) {
    __shared__ float smem[11648];   // 46592 B
    const int tid = threadIdx.x;
    if (blockIdx.x < 101) {
        float* sRowT = smem;            // 32*73
        float* sEmb  = smem + 2336;     // 192
        int kk = blockIdx.x;
        const float* src = (kk < 100) ? (rW3 + kk * 2304) : rb3;
        for (int idx = tid; idx < 2304; idx += 256) {
            int lu = idx >> 5, v = idx & 31;
            sRowT[v * 73 + lu] = src[idx];
        }
        if (tid < 192) sEmb[tid] = emb[tid];
        __syncthreads();
        for (int o = tid; o < 480; o += 256) {
            int e = o / 80, t = o - e * 80;
            float out = 0.0f;
            if (t < 72) {
                float acc = 0.0f;
                #pragma unroll
                for (int v = 0; v < 32; v++) acc += sRowT[v * 73 + t] * sEmb[e * 32 + v];
                out = acc * 0.17677669529663687f;
            }
            g_Wfe[e * 8080 + kk * 80 + t] = out;
        }
    } else {
        float* sW2 = smem;              // 10000
        float* sh1 = smem + 10000;      // 800
        float* sBa = smem + 10800;      // 24
        const int d0 = (blockIdx.x - 101) * 8;
        for (int idx = tid; idx < 10000; idx += 256) sW2[idx] = rW2[idx];
        if (tid < 24) {
            int s = tid & 7, r = tid >> 3;
            float d = (float)(d0 + s) * (2.0f / (float)(TABN - 1));
            float uu = fabsf(d - (float)r);
            float c = __cosf(1.57079632679f * uu);
            sBa[r * 8 + s] = (uu < 1.0f) ? c * c : 0.0f;
        }
        __syncthreads();
        for (int idx = tid; idx < 800; idx += 256) {
            int s = idx & 7, k = idx >> 3;
            float z = rb1[k] + sBa[s] * rW1[k] + sBa[8 + s] * rW1[100 + k] + sBa[16 + s] * rW1[200 + k];
            sh1[k * 8 + s] = sp5(z);
        }
        __syncthreads();
        for (int idx = tid; idx < 800; idx += 256) {
            int s = idx / 100, k2 = idx - s * 100;
            float acc = rb2[k2];
            #pragma unroll 4
            for (int k1 = 0; k1 < 100; k1++) acc += sh1[k1 * 8 + s] * sW2[k1 * 100 + k2];
            g_H2T[k2 * TABN + d0 + s] = sp5(acc);
        }
    }
}

// ---------------- T[e][d][lu] = H2[d] @ Wfe[e] + bias ----------------
#define TT_SMEM ((8080 + 6400) * 4)
__global__ void __launch_bounds__(256) kTtab() {
    extern __shared__ float sm[];
    float* sWf = sm;           // 8080
    float* sA  = sm + 8080;    // [k][dd] 100*64
    const int tid = threadIdx.x;
    const int e = blockIdx.x >> 2, d0 = (blockIdx.x & 3) * 64;   // 24 blocks
    {
        const float4* srcW = (const float4*)(g_Wfe + e * 8080);
        float4* dstW = (float4*)sWf;
        for (int idx = tid; idx < 2020; idx += 256) dstW[idx] = srcW[idx];
    }
    for (int idx = tid; idx < 6400; idx += 256) {
        int k = idx >> 6, dd = idx & 63;
        sA[idx] = g_H2T[k * TABN + d0 + dd];
    }
    __syncthreads();
    const int dg = tid >> 4, lg = tid & 15;
    const int dd0 = dg << 2, lu0 = lg * 5;
    float a0[5], a1[5], a2[5], a3[5];
    #pragma unroll
    for (int t = 0; t < 5; t++) {
        float bb = sWf[8000 + lu0 + t];
        a0[t] = bb; a1[t] = bb; a2[t] = bb; a3[t] = bb;
    }
    #pragma unroll 2
    for (int k = 0; k < 100; k++) {
        float4 a = *(const float4*)(sA + (k << 6) + dd0);
        const float* wr = sWf + k * 80 + lu0;
        #pragma unroll
        for (int t = 0; t < 5; t++) {
            float w = wr[t];
            a0[t] += a.x * w; a1[t] += a.y * w; a2[t] += a.z * w; a3[t] += a.w * w;
        }
    }
    #pragma unroll
    for (int t = 0; t < 5; t++) {
        int lu = lu0 + t;
        if (lu < 72) {
            g_T[(e * TABN + d0 + dd0 + 0) * 72 + lu] = a0[t];
            g_T[(e * TABN + d0 + dd0 + 1) * 72 + lu] = a1[t];
            g_T[(e * TABN + d0 + dd0 + 2) * 72 + lu] = a2[t];
            g_T[(e * TABN + d0 + dd0 + 3) * 72 + lu] = a3[t];
        }
    }
}

// ---------------- gather: per (b,i): lerp-combined T rows, contract with mask*Y ----------------
__global__ void __launch_bounds__(512) kGather(const float* __restrict__ xyz,
                                               const int* __restrict__ feat,
                                               const float* __restrict__ emb) {
    __shared__ float sTl[64 * 72];    // lerp-combined T row per neighbor (18 KB)
    __shared__ float sY[64 * 12];     // mask*Y per neighbor
    __shared__ float sF2[64 * 2];     // lerp weights (1-f, f)
    __shared__ int   sBase[64];
    __shared__ float sPar[216];       // jj-half partials
    __shared__ float sMsum[2];
    __shared__ float sInv;
    const int bi = blockIdx.x;
    const int b = bi >> 6, i = bi & 63;
    const int tid = threadIdx.x;  // 512
    if (tid < 64) {
        int jj = tid;
        float dx = xyz[(b * 64 + jj) * 3 + 0] - xyz[bi * 3 + 0];
        float dy = xyz[(b * 64 + jj) * 3 + 1] - xyz[bi * 3 + 1];
        float dz = xyz[(b * 64 + jj) * 3 + 2] - xyz[bi * 3 + 2];
        float d = sqrtf(dx * dx + dy * dy + dz * dz + 1e-8f);
        float m = (d < 2.0f && jj != i) ? 1.0f : 0.0f;
        float inv = 1.0f / d;
        float ux = dx * inv, uy = dy * inv, uz = dz * inv;
        float db = d * ((float)(TABN - 1) * 0.5f);
        int bin = (int)db;
        bin = (bin > TABN - 2) ? (TABN - 2) : bin;
        float f = db - (float)bin;
        sBase[jj] = (feat[b * 64 + jj] * TABN + bin) * 72;
        sF2[2 * jj]     = 1.0f - f;
        sF2[2 * jj + 1] = f;
        float* yr = sY + jj * 12;
        yr[0] = m * 0.28209479177f;
        yr[1] = m * 0.48860251190f * uy;
        yr[2] = m * 0.48860251190f * uz;
        yr[3] = m * 0.48860251190f * ux;
        yr[4] = m * 1.09254843059f * ux * uy;
        yr[5] = m * 1.09254843059f * uy * uz;
        yr[6] = m * 0.31539156525f * (3.0f * uz * uz - 1.0f);
        yr[7] = m * 1.09254843059f * ux * uz;
        yr[8] = m * 0.54627421529f * (ux * ux - uy * uy);
        float s = m;
        #pragma unroll
        for (int o = 16; o > 0; o >>= 1) s += __shfl_down_sync(0xffffffffu, s, o);
        if ((tid & 31) == 0) sMsum[tid >> 5] = s;
    }
    __syncthreads();
    if (tid == 0) sInv = rsqrtf(fmaxf(sMsum[0] + sMsum[1], 1.0f));
    {
        const int jj = tid >> 3, seg = tid & 7;
        const float4* r1 = (const float4*)(g_T + sBase[jj]);
        const float f1 = sF2[2 * jj], f2 = sF2[2 * jj + 1];
        float4* dst = (float4*)(sTl + jj * 72);
        #pragma unroll
        for (int q = seg; q < 18; q += 8) {
            float4 a = r1[q], c = r1[q + 18];
            float4 o;
            o.x = f1 * a.x + f2 * c.x;
            o.y = f1 * a.y + f2 * c.y;
            o.z = f1 * a.z + f2 * c.z;
            o.w = f1 * a.w + f2 * c.w;
            dst[q] = o;
        }
    }
    __syncthreads();
    {
        int ch = -1, jj0 = 0;
        if (tid < 216)                       { ch = tid;       jj0 = 0;  }
        else if (tid >= 256 && tid < 472)    { ch = tid - 256; jj0 = 32; }
        float acc = 0.0f;
        int lu = 0, ym = 0;
        if (ch >= 0) {
            if (ch < 24)      { lu = ch; ym = 0; }
            else if (ch < 96) { int q = ch - 24; int u = q / 3; ym = 1 + (q - u * 3); lu = 24 + u; }
            else              { int q = ch - 96; int u = q / 5; ym = 4 + (q - u * 5); lu = 48 + u; }
            #pragma unroll 8
            for (int jj = jj0; jj < jj0 + 32; jj++)
                acc += sY[jj * 12 + ym] * sTl[jj * 72 + lu];
            if (jj0 == 32) sPar[ch] = acc;
        }
        __syncthreads();
        if (ch >= 0 && jj0 == 0)
            g_featsT[(32 + ch) * 512 + bi] = (acc + sPar[ch]) * sInv;
        else if (tid >= 216 && tid < 248) {
            int c = tid - 216;
            g_featsT[c * 512 + bi] = emb[feat[bi] * 32 + c];
        }
    }
}

// ---------------- residual GEMM, K-split: 32 tiles (64m x 64n) x 8 K-chunks of 31; 512 threads ----------------
__global__ void __launch_bounds__(512) kRes(const float* __restrict__ resW) {
    __shared__ float sA[31 * 64];   // featsT chunk [k][m]
    __shared__ float sB[31 * 64];   // resW  chunk [k][n]
    const int tid = threadIdx.x;
    const int tile = blockIdx.x & 31;
    const int kc   = blockIdx.x >> 5;
    const int m0 = (tile & 7) * 64;
    const int n0 = (tile >> 3) * 64;
    const int kb = kc * 31;
    const int tx = tid & 15, ty = tid >> 4;   // tx -> 4m, ty (0..31) -> 2n

    for (int idx = tid; idx < 1984; idx += 512) {
        int r = idx >> 6, mm = idx & 63;
        sA[idx] = g_featsT[(kb + r) * 512 + m0 + mm];
        int n = n0 + mm;
        sB[idx] = (n < CO) ? resW[(kb + r) * CO + n] : 0.0f;
    }
    __syncthreads();

    float acc[2][4];
    #pragma unroll
    for (int p = 0; p < 2; p++)
        #pragma unroll
        for (int q = 0; q < 4; q++) acc[p][q] = 0.0f;

    #pragma unroll
    for (int r = 0; r < 31; r++) {
        float4 a  = *(const float4*)(sA + (r << 6) + (tx << 2));
        float2 bv = *(const float2*)(sB + (r << 6) + (ty << 1));
        acc[0][0] += bv.x * a.x; acc[0][1] += bv.x * a.y; acc[0][2] += bv.x * a.z; acc[0][3] += bv.x * a.w;
        acc[1][0] += bv.y * a.x; acc[1][1] += bv.y * a.y; acc[1][2] += bv.y * a.z; acc[1][3] += bv.y * a.w;
    }

    #pragma unroll
    for (int p = 0; p < 2; p++) {
        int n = n0 + (ty << 1) + p;
        float4 st;
        st.x = acc[p][0]; st.y = acc[p][1]; st.z = acc[p][2]; st.w = acc[p][3];
        *(float4*)(g_x2p + ((kc << 8) + n) * 512 + m0 + (tx << 2)) = st;
    }
}

// ---------------- per-column (2 per block): sum K-partials (+resb), BN+relu, per-b mean pool ----------------
__global__ void __launch_bounds__(256) kPool(const float* __restrict__ gamma,
                                             const float* __restrict__ beta,
                                             const float* __restrict__ resb) {
    __shared__ float rs[2][4], rss[2][4];
    __shared__ float sSc[2], sSh[2];
    __shared__ float sP[2][8];
    const int tid = threadIdx.x;       // 256
    const int half = tid >> 7, lt = tid & 127;
    const int w4 = (lt >> 5), lane = tid & 31;   // warp-within-half 0..3
    const int c = blockIdx.x * 2 + half;         // grid 248
    if (tid < 16) sP[tid >> 3][tid & 7] = 0.0f;

    float v[4];
    const bool isx2 = (c >= CO);
    if (!isx2) {
        #pragma unroll
        for (int t = 0; t < 4; t++) v[t] = g_featsT[c * 512 + lt + 128 * t];
    } else {
        int c2 = c - CO;
        float bb = resb[c2];
        #pragma unroll
        for (int t = 0; t < 4; t++) v[t] = bb;
        #pragma unroll
        for (int q = 0; q < 8; q++) {
            const float* row = g_x2p + ((q << 8) + c2) * 512 + lt;
            #pragma unroll
            for (int t = 0; t < 4; t++) v[t] += row[128 * t];
        }
    }
    // stats (computed unconditionally to keep syncs uniform)
    {
        float s = v[0] + v[1] + v[2] + v[3];
        float ss = v[0] * v[0] + v[1] * v[1] + v[2] * v[2] + v[3] * v[3];
        #pragma unroll
        for (int o = 16; o > 0; o >>= 1) {
            s  += __shfl_down_sync(0xffffffffu, s, o);
            ss += __shfl_down_sync(0xffffffffu, ss, o);
        }
        if (lane == 0) { rs[half][w4] = s; rss[half][w4] = ss; }
    }
    __syncthreads();
    if (lt == 0) {
        float S = rs[half][0] + rs[half][1] + rs[half][2] + rs[half][3];
        float SS = rss[half][0] + rss[half][1] + rss[half][2] + rss[half][3];
        float mu = S * (1.0f / 512.0f);
        float var = SS * (1.0f / 512.0f) - mu * mu;
        if (isx2) {
            int c2 = c - CO;
            float sc = gamma[c2] * rsqrtf(var + 1e-5f);
            sSc[half] = sc;
            sSh[half] = beta[c2] - mu * sc;
        } else {
            sSc[half] = 1.0f; sSh[half] = 0.0f;
        }
    }
    __syncthreads();
    if (isx2) {
        float sc = sSc[half], sh = sSh[half];
        #pragma unroll
        for (int t = 0; t < 4; t++) v[t] = fmaxf(v[t] * sc + sh, 0.0f);
    }
    // pooling: warp w4 covers rows [w4*32, w4*32+32) + 128t -> b = (w4>>1) + 2t (warp-uniform)
    #pragma unroll
    for (int t = 0; t < 4; t++) {
        float p = v[t];
        #pragma unroll
        for (int o = 16; o > 0; o >>= 1) p += __shfl_down_sync(0xffffffffu, p, o);
        if (lane == 0) atomicAdd(&sP[half][(w4 >> 1) + 2 * t], p);
    }
    __syncthreads();
    if (tid < 16) {
        int hh = tid >> 3, bq = tid & 7;
        g_pooled[bq * RO + blockIdx.x * 2 + hh] = sP[hh][bq] * (1.0f / 64.0f);
    }
}

// ---------------- head + last-block output ----------------
__global__ void kHead(const float* __restrict__ cW, const float* __restrict__ cb,
                      const float* __restrict__ cg, const float* __restrict__ cbeta,
                      const float* __restrict__ oW, const float* __restrict__ ob,
                      float* __restrict__ out) {
    __shared__ float sPart[8][8];
    __shared__ float sV[8];
    __shared__ float sMu, sIs;
    __shared__ unsigned int sIsLast;
    int ff = blockIdx.x;       // 128
    int tid = threadIdx.x;     // 256
    int lane = tid & 31, w = tid >> 5;
    float p[8];
    #pragma unroll
    for (int q = 0; q < 8; q++) p[q] = 0.0f;
    for (int c = tid; c < RO; c += 256) {
        float wv = cW[c * FFW + ff];
        #pragma unroll
        for (int q = 0; q < 8; q++) p[q] += g_pooled[q * RO + c] * wv;
    }
    #pragma unroll
    for (int q = 0; q < 8; q++) {
        #pragma unroll
        for (int o = 16; o > 0; o >>= 1) p[q] += __shfl_down_sync(0xffffffffu, p[q], o);
    }
    if (lane == 0) {
        #pragma unroll
        for (int q = 0; q < 8; q++) sPart[q][w] = p[q];
    }
    __syncthreads();
    if (tid < 8) {
        float h = cb[ff];
        for (int q = 0; q < 8; q++) h += sPart[tid][q];
        sV[tid] = (h > 0.0f) ? h : 0.01f * h;
    }
    __syncthreads();
    if (tid == 0) {
        float S = 0.0f, SS = 0.0f;
        for (int q = 0; q < 8; q++) { S += sV[q]; SS += sV[q] * sV[q]; }
        float mu = S * 0.125f;
        sMu = mu;
        sIs = rsqrtf(SS * 0.125f - mu * mu + 1e-5f);
    }
    __syncthreads();
    if (tid < 8) {
        float v = (sV[tid] - sMu) * sIs * cg[ff] + cbeta[ff];
        v = (v > 0.0f) ? v : 0.01f * v;
        g_hpart[tid * FFW + ff] = v * oW[ff];
    }
    __syncthreads();
    if (tid == 0) {
        __threadfence();
        sIsLast = (atomicInc(&g_cnt, 127) == 127) ? 1u : 0u;
    }
    __syncthreads();
    if (sIsLast) {
        __threadfence();
        int bq = tid >> 5, ln = tid & 31;
        float s = g_hpart[bq * FFW + ln] + g_hpart[bq * FFW + 32 + ln]
                + g_hpart[bq * FFW + 64 + ln] + g_hpart[bq * FFW + 96 + ln];
        #pragma unroll
        for (int o = 16; o > 0; o >>= 1) s += __shfl_down_sync(0xffffffffu, s, o);
        if (ln == 0) out[bq] = 1.0f / (1.0f + __expf(-(s + ob[0])));
    }
}

extern "C" void kernel_launch(void* const* d_in, const int* in_sizes, int n_in,
                              void* d_out, int out_size) {
    const float* xyz   = (const float*)d_in[0];
    const int*   feat  = (const int*)  d_in[1];
    const float* emb   = (const float*)d_in[2];
    const float* rW1   = (const float*)d_in[3];
    const float* rb1   = (const float*)d_in[4];
    const float* rW2   = (const float*)d_in[5];
    const float* rb2   = (const float*)d_in[6];
    const float* rW3   = (const float*)d_in[7];
    const float* rb3   = (const float*)d_in[8];
    const float* resW  = (const float*)d_in[9];
    const float* resb  = (const float*)d_in[10];
    const float* resg  = (const float*)d_in[11];
    const float* resbe = (const float*)d_in[12];
    const float* cW    = (const float*)d_in[13];
    const float* cb    = (const float*)d_in[14];
    const float* cg    = (const float*)d_in[15];
    const float* cbe   = (const float*)d_in[16];
    const float* oW    = (const float*)d_in[17];
    const float* ob    = (const float*)d_in[18];
    float* out = (float*)d_out;

    cudaFuncSetAttribute(kTtab, cudaFuncAttributeMaxDynamicSharedMemorySize, TT_SMEM);

    kPrep<<<101 + TABN / 8, 256>>>(rW3, rb3, emb, rW1, rb1, rW2, rb2);
    kTtab<<<6 * (TABN / 64), 256, TT_SMEM>>>();
    kGather<<<512, 512>>>(xyz, feat, emb);
    kRes<<<256, 512>>>(resW);
    kPool<<<248, 256>>>(resg, resbe, resb);
    kHead<<<128, 256>>>(cW, cb, cg, cbe, oW, ob, out);
}